// round 2
// baseline (speedup 1.0000x reference)
#include <cuda_runtime.h>

#define NB 8
#define CDIM 512
#define NHEADS 8
#define HD 64
#define NT 4096           // H*W = 64*64

// ---------------- scratch (device globals: alloc-free) ----------------
__device__ float g_qkvo[(size_t)NB * 2048 * NT];   // 268 MB
__device__ float g_lepe[(size_t)NB * CDIM * NT];   // 67 MB
__device__ float g_y   [(size_t)NB * CDIM * NT];   // 67 MB
__device__ float g_eff [NB * NHEADS * NT];
__device__ float g_kv  [NB * NHEADS * HD * HD];
__device__ float g_km  [NB * NHEADS * HD];

__device__ __forceinline__ float elu1(float x) { return x > 0.f ? x + 1.f : __expf(x); }

__device__ __forceinline__ float warpSum(float v) {
#pragma unroll
    for (int o = 16; o > 0; o >>= 1) v += __shfl_xor_sync(0xffffffffu, v, o);
    return v;
}
__device__ __forceinline__ float warpMax(float v) {
#pragma unroll
    for (int o = 16; o > 0; o >>= 1) v = fmaxf(v, __shfl_xor_sync(0xffffffffu, v, o));
    return v;
}

// ---------------- zero accumulators (must run every graph replay) ----------------
__global__ void zero_kernel() {
    int i = blockIdx.x * blockDim.x + threadIdx.x;
    if (i < NB * NHEADS * HD * HD) g_kv[i] = 0.f;
    if (i < NB * NHEADS * HD)      g_km[i] = 0.f;
}

// ---------------- batched GEMM: C[b] = A[M,K] @ X[b][K,N] + bias ----------------
// 128x128 tile, BK=16, 256 threads, 8x8 microtile. All dims divide evenly here.
__global__ void __launch_bounds__(256) gemm_bias_kernel(
    const float* __restrict__ A, const float* __restrict__ X,
    const float* __restrict__ bias, float* __restrict__ C,
    int M, int K, int N)
{
    const int b = blockIdx.z;
    const float* Xb = X + (size_t)b * K * N;
    float*       Cb = C + (size_t)b * M * N;
    const int m0 = blockIdx.y * 128, n0 = blockIdx.x * 128;

    __shared__ float As[16][128];
    __shared__ float Bs[16][128];

    const int tid = threadIdx.x;
    const int tx = tid & 15, ty = tid >> 4;

    float acc[8][8];
#pragma unroll
    for (int i = 0; i < 8; i++)
#pragma unroll
        for (int j = 0; j < 8; j++) acc[i][j] = 0.f;

    for (int k0 = 0; k0 < K; k0 += 16) {
#pragma unroll
        for (int l = 0; l < 2; l++) {
            int id = tid + l * 256;
            int ar = id >> 2;            // 0..127
            int ac = (id & 3) * 4;       // 0,4,8,12
            float4 av = *(const float4*)&A[(size_t)(m0 + ar) * K + k0 + ac];
            As[ac + 0][ar] = av.x; As[ac + 1][ar] = av.y;
            As[ac + 2][ar] = av.z; As[ac + 3][ar] = av.w;
        }
#pragma unroll
        for (int l = 0; l < 2; l++) {
            int id = tid + l * 256;
            int br = id >> 5;            // 0..15
            int bc = (id & 31) * 4;      // 0..124
            *(float4*)&Bs[br][bc] = *(const float4*)&Xb[(size_t)(k0 + br) * N + n0 + bc];
        }
        __syncthreads();
#pragma unroll
        for (int k = 0; k < 16; k++) {
            float a[8], bb[8];
#pragma unroll
            for (int i = 0; i < 8; i++) a[i] = As[k][ty * 8 + i];
#pragma unroll
            for (int j = 0; j < 8; j++) bb[j] = Bs[k][tx * 8 + j];
#pragma unroll
            for (int i = 0; i < 8; i++)
#pragma unroll
                for (int j = 0; j < 8; j++) acc[i][j] += a[i] * bb[j];
        }
        __syncthreads();
    }

#pragma unroll
    for (int i = 0; i < 8; i++) {
        int m = m0 + ty * 8 + i;
        float bv = bias[m];
        float4 v0 = make_float4(acc[i][0] + bv, acc[i][1] + bv, acc[i][2] + bv, acc[i][3] + bv);
        float4 v1 = make_float4(acc[i][4] + bv, acc[i][5] + bv, acc[i][6] + bv, acc[i][7] + bv);
        *(float4*)&Cb[(size_t)m * N + n0 + tx * 8 + 0] = v0;
        *(float4*)&Cb[(size_t)m * N + n0 + tx * 8 + 4] = v1;
    }
}

// ---------------- depthwise 5x5 conv on v channels -> g_lepe ----------------
__global__ void __launch_bounds__(256) conv_kernel(
    const float* __restrict__ w_lepe, const float* __restrict__ b_lepe)
{
    const int bc = blockIdx.x;
    const int b = bc >> 9, c = bc & 511;
    __shared__ float wsh[25];
    const int tid = threadIdx.x;
    if (tid < 25) wsh[tid] = w_lepe[c * 25 + tid];
    __syncthreads();

    const int y = blockIdx.y * 4 + (tid >> 6);
    const int xw = tid & 63;
    const float* Vp = g_qkvo + ((size_t)b * 2048 + 1024 + c) * NT;

    float acc = b_lepe[c];
#pragma unroll
    for (int i = 0; i < 5; i++) {
        int yy = y + i - 2;
        if (yy < 0 || yy >= 64) continue;
#pragma unroll
        for (int j = 0; j < 5; j++) {
            int xx = xw + j - 2;
            if (xx < 0 || xx >= 64) continue;
            acc += wsh[i * 5 + j] * Vp[yy * 64 + xx];
        }
    }
    g_lepe[((size_t)b * 512 + c) * NT + y * 64 + xw] = acc;
}

// ---------------- per (b,h): q_mean -> logits -> softmax -> g_eff ----------------
__global__ void __launch_bounds__(256) stats_kernel()
{
    const int bh = blockIdx.x;
    const int b = bh >> 3, h = bh & 7;
    const float* Q  = g_qkvo + ((size_t)b * 2048 +       h * 64) * NT;
    const float* Kp = g_qkvo + ((size_t)b * 2048 + 512 + h * 64) * NT;

    __shared__ float sqm[64];
    __shared__ float red[8];
    const int tid = threadIdx.x;
    const int lane = tid & 31, wid = tid >> 5;

    if (tid < 64) sqm[tid] = 0.f;
    __syncthreads();

    // q_mean sums (atomic into smem; 64 rows x 4096)
    for (int d = 0; d < 64; d++) {
        float p = 0.f;
#pragma unroll
        for (int i = 0; i < 16; i++) p += elu1(Q[(size_t)d * NT + tid + i * 256]);
        p = warpSum(p);
        if (lane == 0) atomicAdd(&sqm[d], p);
    }
    __syncthreads();

    // logits
    float l[16];
#pragma unroll
    for (int i = 0; i < 16; i++) l[i] = 0.f;
    for (int d = 0; d < 64; d++) {
        float km = sqm[d] * (1.f / NT);
#pragma unroll
        for (int i = 0; i < 16; i++) l[i] += km * elu1(Kp[(size_t)d * NT + tid + i * 256]);
    }
    float mx = -1e30f;
#pragma unroll
    for (int i = 0; i < 16; i++) { l[i] *= 0.125f; mx = fmaxf(mx, l[i]); }

    // block max
    mx = warpMax(mx);
    if (lane == 0) red[wid] = mx;
    __syncthreads();
    if (tid == 0) {
        float m = red[0];
        for (int w = 1; w < 8; w++) m = fmaxf(m, red[w]);
        red[0] = m;
    }
    __syncthreads();
    mx = red[0];
    __syncthreads();

    // block sum of exp
    float s = 0.f;
#pragma unroll
    for (int i = 0; i < 16; i++) s += __expf(l[i] - mx);
    s = warpSum(s);
    if (lane == 0) red[wid] = s;
    __syncthreads();
    if (tid == 0) {
        float ss = 0.f;
        for (int w = 0; w < 8; w++) ss += red[w];
        red[0] = ss;
    }
    __syncthreads();
    const float inv = 1.f / red[0];

#pragma unroll
    for (int i = 0; i < 16; i++)
        g_eff[bh * NT + tid + i * 256] = __expf(l[i] - mx) * inv;
}

// ---------------- kv[d,e] = sum_t rope(k*eff)[t,d]*v[t,e];  km[d] = sum_t k*eff ----------------
__global__ void __launch_bounds__(256) kv_kernel(
    const float* __restrict__ sinp, const float* __restrict__ cosp)
{
    const int bh = blockIdx.x;
    const int b = bh >> 3, h = bh & 7;
    const int chunk = blockIdx.y;   // 8 chunks of 512 t
    const float* Kp  = g_qkvo + ((size_t)b * 2048 +  512 + h * 64) * NT;
    const float* Vp  = g_qkvo + ((size_t)b * 2048 + 1024 + h * 64) * NT;
    const float* eff = g_eff + bh * NT;

    __shared__ float sk[64][65];   // [t][d]
    __shared__ float sv[64][65];   // [t][e]

    const int tid = threadIdx.x;
    const int ttl = tid & 63;      // t within tile (consecutive across threads -> coalesced)
    const int drow = tid >> 6;     // 0..3
    const int d0 = (tid & 15) * 4, e0 = (tid >> 4) * 4;

    float acc[4][4];
#pragma unroll
    for (int i = 0; i < 4; i++)
#pragma unroll
        for (int j = 0; j < 4; j++) acc[i][j] = 0.f;
    float kmacc = 0.f;

    for (int tile = 0; tile < 8; tile++) {
        const int t0 = chunk * 512 + tile * 64;
        const float effv = eff[t0 + ttl];
#pragma unroll
        for (int r = 0; r < 16; r++) {
            int d = drow + r * 4;
            sk[ttl][d] = elu1(Kp[(size_t)d * NT + t0 + ttl]) * effv;
            sv[ttl][d] = Vp[(size_t)d * NT + t0 + ttl];
        }
        __syncthreads();

        // kmean partial (raw k*eff) -- read-only phase
        if (tid < 64) {
#pragma unroll 8
            for (int tt = 0; tt < 64; tt++) kmacc += sk[tt][tid];
        }
        // rope into registers (read-only phase)
        float r0[8], r1[8];
        const int t = t0 + ttl;
#pragma unroll
        for (int r = 0; r < 8; r++) {
            int pr = drow + r * 4;          // pair id 0..31
            int d = 2 * pr;
            float a  = sk[ttl][d];
            float bb = sk[ttl][d + 1];
            float c0 = cosp[t * 64 + d],     s0 = sinp[t * 64 + d];
            float c1 = cosp[t * 64 + d + 1], s1 = sinp[t * 64 + d + 1];
            r0[r] = a * c0 - bb * s0;
            r1[r] = bb * c1 + a * s1;
        }
        __syncthreads();
#pragma unroll
        for (int r = 0; r < 8; r++) {
            int d = 2 * (drow + r * 4);
            sk[ttl][d]     = r0[r];
            sk[ttl][d + 1] = r1[r];
        }
        __syncthreads();

        // accumulate kv outer products
#pragma unroll 4
        for (int tt = 0; tt < 64; tt++) {
            float kk[4], vv[4];
#pragma unroll
            for (int j = 0; j < 4; j++) { kk[j] = sk[tt][d0 + j]; vv[j] = sv[tt][e0 + j]; }
#pragma unroll
            for (int i = 0; i < 4; i++)
#pragma unroll
                for (int j = 0; j < 4; j++) acc[i][j] += kk[i] * vv[j];
        }
        __syncthreads();
    }

    float* kvout = g_kv + (size_t)bh * HD * HD;
#pragma unroll
    for (int i = 0; i < 4; i++)
#pragma unroll
        for (int j = 0; j < 4; j++)
            atomicAdd(&kvout[(d0 + i) * 64 + e0 + j], acc[i][j]);
    if (tid < 64) atomicAdd(&g_km[bh * 64 + tid], kmacc);
}

// ---------------- res[t,e] = z[t] * sum_d rope(q)[t,d]*kv[d,e]; y = (res+lepe)*gate ----------------
__global__ void __launch_bounds__(256) res_kernel(
    const float* __restrict__ sinp, const float* __restrict__ cosp)
{
    const int bh = blockIdx.x;
    const int b = bh >> 3, h = bh & 7;
    const int tid = threadIdx.x;
    const int t = blockIdx.y * 256 + tid;
    const float* Q = g_qkvo + ((size_t)b * 2048 + h * 64) * NT;

    __shared__ float skv[64][64];
    __shared__ float skm[64];
#pragma unroll
    for (int r = 0; r < 16; r++)
        ((float*)skv)[tid + r * 256] = g_kv[(size_t)bh * 4096 + tid + r * 256];
    if (tid < 64) skm[tid] = g_km[bh * 64 + tid];
    __syncthreads();

    float res[64];
#pragma unroll
    for (int e = 0; e < 64; e++) res[e] = 0.f;
    float zacc = 0.f;

    for (int p = 0; p < 32; p++) {
        const int d = 2 * p;
        float q0 = elu1(Q[(size_t)d * NT + t]);
        float q1 = elu1(Q[(size_t)(d + 1) * NT + t]);
        zacc += q0 * skm[d] + q1 * skm[d + 1];
        float c0 = cosp[t * 64 + d],     s0 = sinp[t * 64 + d];
        float c1 = cosp[t * 64 + d + 1], s1 = sinp[t * 64 + d + 1];
        float qr0 = q0 * c0 - q1 * s0;
        float qr1 = q1 * c1 + q0 * s1;
        const float4* kv0 = (const float4*)skv[d];
        const float4* kv1 = (const float4*)skv[d + 1];
#pragma unroll
        for (int e4 = 0; e4 < 16; e4++) {
            float4 a = kv0[e4], bb = kv1[e4];
            res[e4 * 4 + 0] += qr0 * a.x + qr1 * bb.x;
            res[e4 * 4 + 1] += qr0 * a.y + qr1 * bb.y;
            res[e4 * 4 + 2] += qr0 * a.z + qr1 * bb.z;
            res[e4 * 4 + 3] += qr0 * a.w + qr1 * bb.w;
        }
    }
    const float z = 1.f / (zacc + 1e-6f);

#pragma unroll 8
    for (int e = 0; e < 64; e++) {
        int c = h * 64 + e;
        size_t idx = ((size_t)b * 512 + c) * NT + t;
        float gate = g_qkvo[((size_t)b * 2048 + 1536 + c) * NT + t];
        g_y[idx] = (res[e] * z + g_lepe[idx]) * gate;
    }
}

// ---------------- launch ----------------
extern "C" void kernel_launch(void* const* d_in, const int* in_sizes, int n_in,
                              void* d_out, int out_size)
{
    const float* x      = (const float*)d_in[0];
    const float* sinp   = (const float*)d_in[1];
    const float* cosp   = (const float*)d_in[2];
    const float* w_qkvo = (const float*)d_in[3];
    const float* b_qkvo = (const float*)d_in[4];
    const float* w_lepe = (const float*)d_in[5];
    const float* b_lepe = (const float*)d_in[6];
    const float* w_proj = (const float*)d_in[7];
    const float* b_proj = (const float*)d_in[8];
    float* out = (float*)d_out;

    float *qkvo_p = nullptr, *y_p = nullptr;
    cudaGetSymbolAddress((void**)&qkvo_p, g_qkvo);
    cudaGetSymbolAddress((void**)&y_p,    g_y);

    zero_kernel<<<(NB * NHEADS * HD * HD + 255) / 256, 256>>>();

    dim3 g1(NT / 128, 2048 / 128, NB);
    gemm_bias_kernel<<<g1, 256>>>(w_qkvo, x, b_qkvo, qkvo_p, 2048, 512, NT);

    conv_kernel<<<dim3(NB * CDIM, 16), 256>>>(w_lepe, b_lepe);

    stats_kernel<<<NB * NHEADS, 256>>>();

    kv_kernel<<<dim3(NB * NHEADS, 8), 256>>>(sinp, cosp);

    res_kernel<<<dim3(NB * NHEADS, 16), 256>>>(sinp, cosp);

    dim3 g2(NT / 128, 512 / 128, NB);
    gemm_bias_kernel<<<g2, 256>>>(w_proj, y_p, b_proj, out, 512, 512, NT);
}

// round 3
// speedup vs baseline: 1.0075x; 1.0075x over previous
#include <cuda_runtime.h>

#define NB 8
#define CDIM 512
#define NHEADS 8
#define HD 64
#define NT 4096           // H*W = 64*64

// ---------------- scratch (device globals: alloc-free) ----------------
__device__ float g_qkvo[(size_t)NB * 2048 * NT];   // 268 MB
__device__ float g_lepe[(size_t)NB * CDIM * NT];   // 67 MB
__device__ float g_y   [(size_t)NB * CDIM * NT];   // 67 MB
__device__ float g_eff [NB * NHEADS * NT];
__device__ float g_kv  [NB * NHEADS * HD * HD];
__device__ float g_km  [NB * NHEADS * HD];

__device__ __forceinline__ float elu1(float x) { return x > 0.f ? x + 1.f : __expf(x); }

__device__ __forceinline__ float warpSum(float v) {
#pragma unroll
    for (int o = 16; o > 0; o >>= 1) v += __shfl_xor_sync(0xffffffffu, v, o);
    return v;
}
__device__ __forceinline__ float warpMax(float v) {
#pragma unroll
    for (int o = 16; o > 0; o >>= 1) v = fmaxf(v, __shfl_xor_sync(0xffffffffu, v, o));
    return v;
}

// ---------------- zero accumulators (must run every graph replay) ----------------
__global__ void zero_kernel() {
    int i = blockIdx.x * blockDim.x + threadIdx.x;
    if (i < NB * NHEADS * HD * HD) g_kv[i] = 0.f;
    if (i < NB * NHEADS * HD)      g_km[i] = 0.f;
}

// ---------------- batched GEMM: C[b] = A[M,K] @ X[b][K,N] + bias ----------------
// 128x128 tile, BK=16, 256 threads, 8x8 microtile. All dims divide evenly here.
__global__ void __launch_bounds__(256) gemm_bias_kernel(
    const float* __restrict__ A, const float* __restrict__ X,
    const float* __restrict__ bias, float* __restrict__ C,
    int M, int K, int N)
{
    const int b = blockIdx.z;
    const float* Xb = X + (size_t)b * K * N;
    float*       Cb = C + (size_t)b * M * N;
    const int m0 = blockIdx.y * 128, n0 = blockIdx.x * 128;

    __shared__ float As[16][128];
    __shared__ float Bs[16][128];

    const int tid = threadIdx.x;
    const int tx = tid & 15, ty = tid >> 4;

    float acc[8][8];
#pragma unroll
    for (int i = 0; i < 8; i++)
#pragma unroll
        for (int j = 0; j < 8; j++) acc[i][j] = 0.f;

    for (int k0 = 0; k0 < K; k0 += 16) {
#pragma unroll
        for (int l = 0; l < 2; l++) {
            int id = tid + l * 256;
            int ar = id >> 2;            // 0..127
            int ac = (id & 3) * 4;       // 0,4,8,12
            float4 av = *(const float4*)&A[(size_t)(m0 + ar) * K + k0 + ac];
            As[ac + 0][ar] = av.x; As[ac + 1][ar] = av.y;
            As[ac + 2][ar] = av.z; As[ac + 3][ar] = av.w;
        }
#pragma unroll
        for (int l = 0; l < 2; l++) {
            int id = tid + l * 256;
            int br = id >> 5;            // 0..15
            int bc = (id & 31) * 4;      // 0..124
            *(float4*)&Bs[br][bc] = *(const float4*)&Xb[(size_t)(k0 + br) * N + n0 + bc];
        }
        __syncthreads();
#pragma unroll
        for (int k = 0; k < 16; k++) {
            float a[8], bb[8];
#pragma unroll
            for (int i = 0; i < 8; i++) a[i] = As[k][ty * 8 + i];
#pragma unroll
            for (int j = 0; j < 8; j++) bb[j] = Bs[k][tx * 8 + j];
#pragma unroll
            for (int i = 0; i < 8; i++)
#pragma unroll
                for (int j = 0; j < 8; j++) acc[i][j] += a[i] * bb[j];
        }
        __syncthreads();
    }

#pragma unroll
    for (int i = 0; i < 8; i++) {
        int m = m0 + ty * 8 + i;
        float bv = bias[m];
        float4 v0 = make_float4(acc[i][0] + bv, acc[i][1] + bv, acc[i][2] + bv, acc[i][3] + bv);
        float4 v1 = make_float4(acc[i][4] + bv, acc[i][5] + bv, acc[i][6] + bv, acc[i][7] + bv);
        *(float4*)&Cb[(size_t)m * N + n0 + tx * 8 + 0] = v0;
        *(float4*)&Cb[(size_t)m * N + n0 + tx * 8 + 4] = v1;
    }
}

// ---------------- depthwise 5x5 conv on v channels -> g_lepe ----------------
__global__ void __launch_bounds__(256) conv_kernel(
    const float* __restrict__ w_lepe, const float* __restrict__ b_lepe)
{
    const int bc = blockIdx.x;
    const int b = bc >> 9, c = bc & 511;
    __shared__ float wsh[25];
    const int tid = threadIdx.x;
    if (tid < 25) wsh[tid] = w_lepe[c * 25 + tid];
    __syncthreads();

    const int y = blockIdx.y * 4 + (tid >> 6);
    const int xw = tid & 63;
    const float* Vp = g_qkvo + ((size_t)b * 2048 + 1024 + c) * NT;

    float acc = b_lepe[c];
#pragma unroll
    for (int i = 0; i < 5; i++) {
        int yy = y + i - 2;
        if (yy < 0 || yy >= 64) continue;
#pragma unroll
        for (int j = 0; j < 5; j++) {
            int xx = xw + j - 2;
            if (xx < 0 || xx >= 64) continue;
            acc += wsh[i * 5 + j] * Vp[yy * 64 + xx];
        }
    }
    g_lepe[((size_t)b * 512 + c) * NT + y * 64 + xw] = acc;
}

// ---------------- per (b,h): q_mean -> logits -> softmax -> g_eff ----------------
__global__ void __launch_bounds__(256) stats_kernel()
{
    const int bh = blockIdx.x;
    const int b = bh >> 3, h = bh & 7;
    const float* Q  = g_qkvo + ((size_t)b * 2048 +       h * 64) * NT;
    const float* Kp = g_qkvo + ((size_t)b * 2048 + 512 + h * 64) * NT;

    __shared__ float sqm[64];
    __shared__ float red[8];
    const int tid = threadIdx.x;
    const int lane = tid & 31, wid = tid >> 5;

    if (tid < 64) sqm[tid] = 0.f;
    __syncthreads();

    // q_mean sums (atomic into smem; 64 rows x 4096)
    for (int d = 0; d < 64; d++) {
        float p = 0.f;
#pragma unroll
        for (int i = 0; i < 16; i++) p += elu1(Q[(size_t)d * NT + tid + i * 256]);
        p = warpSum(p);
        if (lane == 0) atomicAdd(&sqm[d], p);
    }
    __syncthreads();

    // logits
    float l[16];
#pragma unroll
    for (int i = 0; i < 16; i++) l[i] = 0.f;
    for (int d = 0; d < 64; d++) {
        float km = sqm[d] * (1.f / NT);
#pragma unroll
        for (int i = 0; i < 16; i++) l[i] += km * elu1(Kp[(size_t)d * NT + tid + i * 256]);
    }
    float mx = -1e30f;
#pragma unroll
    for (int i = 0; i < 16; i++) { l[i] *= 0.125f; mx = fmaxf(mx, l[i]); }

    // block max
    mx = warpMax(mx);
    if (lane == 0) red[wid] = mx;
    __syncthreads();
    if (tid == 0) {
        float m = red[0];
        for (int w = 1; w < 8; w++) m = fmaxf(m, red[w]);
        red[0] = m;
    }
    __syncthreads();
    mx = red[0];
    __syncthreads();

    // block sum of exp
    float s = 0.f;
#pragma unroll
    for (int i = 0; i < 16; i++) s += __expf(l[i] - mx);
    s = warpSum(s);
    if (lane == 0) red[wid] = s;
    __syncthreads();
    if (tid == 0) {
        float ss = 0.f;
        for (int w = 0; w < 8; w++) ss += red[w];
        red[0] = ss;
    }
    __syncthreads();
    const float inv = 1.f / red[0];

#pragma unroll
    for (int i = 0; i < 16; i++)
        g_eff[bh * NT + tid + i * 256] = __expf(l[i] - mx) * inv;
}

// ---------------- kv[d,e] = sum_t rope(k*eff)[t,d]*v[t,e];  km[d] = sum_t k*eff ----------------
__global__ void __launch_bounds__(256) kv_kernel(
    const float* __restrict__ sinp, const float* __restrict__ cosp)
{
    const int bh = blockIdx.x;
    const int b = bh >> 3, h = bh & 7;
    const int chunk = blockIdx.y;   // 8 chunks of 512 t
    const float* Kp  = g_qkvo + ((size_t)b * 2048 +  512 + h * 64) * NT;
    const float* Vp  = g_qkvo + ((size_t)b * 2048 + 1024 + h * 64) * NT;
    const float* eff = g_eff + bh * NT;

    __shared__ float sk[64][65];   // [t][d]
    __shared__ float sv[64][65];   // [t][e]

    const int tid = threadIdx.x;
    const int ttl = tid & 63;      // t within tile (consecutive across threads -> coalesced)
    const int drow = tid >> 6;     // 0..3
    const int d0 = (tid & 15) * 4, e0 = (tid >> 4) * 4;

    float acc[4][4];
#pragma unroll
    for (int i = 0; i < 4; i++)
#pragma unroll
        for (int j = 0; j < 4; j++) acc[i][j] = 0.f;
    float kmacc = 0.f;

    for (int tile = 0; tile < 8; tile++) {
        const int t0 = chunk * 512 + tile * 64;
        const float effv = eff[t0 + ttl];
#pragma unroll
        for (int r = 0; r < 16; r++) {
            int d = drow + r * 4;
            sk[ttl][d] = elu1(Kp[(size_t)d * NT + t0 + ttl]) * effv;
            sv[ttl][d] = Vp[(size_t)d * NT + t0 + ttl];
        }
        __syncthreads();

        // kmean partial (raw k*eff) -- read-only phase
        if (tid < 64) {
#pragma unroll 8
            for (int tt = 0; tt < 64; tt++) kmacc += sk[tt][tid];
        }
        // rope into registers (read-only phase)
        float r0[8], r1[8];
        const int t = t0 + ttl;
#pragma unroll
        for (int r = 0; r < 8; r++) {
            int pr = drow + r * 4;          // pair id 0..31
            int d = 2 * pr;
            float a  = sk[ttl][d];
            float bb = sk[ttl][d + 1];
            float c0 = cosp[t * 64 + d],     s0 = sinp[t * 64 + d];
            float c1 = cosp[t * 64 + d + 1], s1 = sinp[t * 64 + d + 1];
            r0[r] = a * c0 - bb * s0;
            r1[r] = bb * c1 + a * s1;
        }
        __syncthreads();
#pragma unroll
        for (int r = 0; r < 8; r++) {
            int d = 2 * (drow + r * 4);
            sk[ttl][d]     = r0[r];
            sk[ttl][d + 1] = r1[r];
        }
        __syncthreads();

        // accumulate kv outer products
#pragma unroll 4
        for (int tt = 0; tt < 64; tt++) {
            float kk[4], vv[4];
#pragma unroll
            for (int j = 0; j < 4; j++) { kk[j] = sk[tt][d0 + j]; vv[j] = sv[tt][e0 + j]; }
#pragma unroll
            for (int i = 0; i < 4; i++)
#pragma unroll
                for (int j = 0; j < 4; j++) acc[i][j] += kk[i] * vv[j];
        }
        __syncthreads();
    }

    float* kvout = g_kv + (size_t)bh * HD * HD;
#pragma unroll
    for (int i = 0; i < 4; i++)
#pragma unroll
        for (int j = 0; j < 4; j++)
            atomicAdd(&kvout[(d0 + i) * 64 + e0 + j], acc[i][j]);
    if (tid < 64) atomicAdd(&g_km[bh * 64 + tid], kmacc);
}

// ---------------- res[t,e] = z[t] * sum_d rope(q)[t,d]*kv[d,e]; y = (res+lepe)*gate ----------------
__global__ void __launch_bounds__(256) res_kernel(
    const float* __restrict__ sinp, const float* __restrict__ cosp)
{
    const int bh = blockIdx.x;
    const int b = bh >> 3, h = bh & 7;
    const int tid = threadIdx.x;
    const int t = blockIdx.y * 256 + tid;
    const float* Q = g_qkvo + ((size_t)b * 2048 + h * 64) * NT;

    __shared__ float skv[64][64];
    __shared__ float skm[64];
#pragma unroll
    for (int r = 0; r < 16; r++)
        ((float*)skv)[tid + r * 256] = g_kv[(size_t)bh * 4096 + tid + r * 256];
    if (tid < 64) skm[tid] = g_km[bh * 64 + tid];
    __syncthreads();

    float res[64];
#pragma unroll
    for (int e = 0; e < 64; e++) res[e] = 0.f;
    float zacc = 0.f;

    for (int p = 0; p < 32; p++) {
        const int d = 2 * p;
        float q0 = elu1(Q[(size_t)d * NT + t]);
        float q1 = elu1(Q[(size_t)(d + 1) * NT + t]);
        zacc += q0 * skm[d] + q1 * skm[d + 1];
        float c0 = cosp[t * 64 + d],     s0 = sinp[t * 64 + d];
        float c1 = cosp[t * 64 + d + 1], s1 = sinp[t * 64 + d + 1];
        float qr0 = q0 * c0 - q1 * s0;
        float qr1 = q1 * c1 + q0 * s1;
        const float4* kv0 = (const float4*)skv[d];
        const float4* kv1 = (const float4*)skv[d + 1];
#pragma unroll
        for (int e4 = 0; e4 < 16; e4++) {
            float4 a = kv0[e4], bb = kv1[e4];
            res[e4 * 4 + 0] += qr0 * a.x + qr1 * bb.x;
            res[e4 * 4 + 1] += qr0 * a.y + qr1 * bb.y;
            res[e4 * 4 + 2] += qr0 * a.z + qr1 * bb.z;
            res[e4 * 4 + 3] += qr0 * a.w + qr1 * bb.w;
        }
    }
    const float z = 1.f / (zacc + 1e-6f);

#pragma unroll 8
    for (int e = 0; e < 64; e++) {
        int c = h * 64 + e;
        size_t idx = ((size_t)b * 512 + c) * NT + t;
        float gate = g_qkvo[((size_t)b * 2048 + 1536 + c) * NT + t];
        g_y[idx] = (res[e] * z + g_lepe[idx]) * gate;
    }
}

// ---------------- launch ----------------
extern "C" void kernel_launch(void* const* d_in, const int* in_sizes, int n_in,
                              void* d_out, int out_size)
{
    const float* x      = (const float*)d_in[0];
    const float* sinp   = (const float*)d_in[1];
    const float* cosp   = (const float*)d_in[2];
    const float* w_qkvo = (const float*)d_in[3];
    const float* b_qkvo = (const float*)d_in[4];
    const float* w_lepe = (const float*)d_in[5];
    const float* b_lepe = (const float*)d_in[6];
    const float* w_proj = (const float*)d_in[7];
    const float* b_proj = (const float*)d_in[8];
    float* out = (float*)d_out;

    float *qkvo_p = nullptr, *y_p = nullptr;
    cudaGetSymbolAddress((void**)&qkvo_p, g_qkvo);
    cudaGetSymbolAddress((void**)&y_p,    g_y);

    zero_kernel<<<(NB * NHEADS * HD * HD + 255) / 256, 256>>>();

    dim3 g1(NT / 128, 2048 / 128, NB);
    gemm_bias_kernel<<<g1, 256>>>(w_qkvo, x, b_qkvo, qkvo_p, 2048, 512, NT);

    conv_kernel<<<dim3(NB * CDIM, 16), 256>>>(w_lepe, b_lepe);

    stats_kernel<<<NB * NHEADS, 256>>>();

    kv_kernel<<<dim3(NB * NHEADS, 8), 256>>>(sinp, cosp);

    res_kernel<<<dim3(NB * NHEADS, 16), 256>>>(sinp, cosp);

    dim3 g2(NT / 128, 512 / 128, NB);
    gemm_bias_kernel<<<g2, 256>>>(w_proj, y_p, b_proj, out, 512, 512, NT);
}

// round 6
// speedup vs baseline: 1.6525x; 1.6401x over previous
#include <cuda_runtime.h>
#include <cuda_bf16.h>
#include <cstdint>

#define NB 8
#define CDIM 512
#define NHEADS 8
#define HD 64
#define NT 4096           // H*W = 64*64

// ---------------- scratch (device globals: alloc-free) ----------------
__device__ float g_qkvo[(size_t)NB * 2048 * NT];   // 268 MB fp32 qkvo
__device__ float g_lepe[(size_t)NB * CDIM * NT];   // 67 MB
__device__ float g_eff [NB * NHEADS * NT];
__device__ float g_kv  [NB * NHEADS * HD * HD];
__device__ float g_km  [NB * NHEADS * HD];
__device__ float g_qm  [NB * NHEADS * HD];

// bf16 hi/lo operand buffers for tensor-core GEMMs
__device__ __nv_bfloat16 g_wqh[2048 * 512], g_wql[2048 * 512];
__device__ __nv_bfloat16 g_wph[512 * 512],  g_wpl[512 * 512];
__device__ __nv_bfloat16 g_xth[(size_t)NB * NT * 512], g_xtl[(size_t)NB * NT * 512];
__device__ __nv_bfloat16 g_yth[(size_t)NB * NT * 512], g_ytl[(size_t)NB * NT * 512];

__device__ __forceinline__ float elu1(float x) { return x > 0.f ? x + 1.f : __expf(x); }

__device__ __forceinline__ float warpSum(float v) {
#pragma unroll
    for (int o = 16; o > 0; o >>= 1) v += __shfl_xor_sync(0xffffffffu, v, o);
    return v;
}
__device__ __forceinline__ float warpMax(float v) {
#pragma unroll
    for (int o = 16; o > 0; o >>= 1) v = fmaxf(v, __shfl_xor_sync(0xffffffffu, v, o));
    return v;
}

__device__ __forceinline__ uint32_t smem_u32(const void* p) {
    uint32_t a;
    asm("{ .reg .u64 t; cvta.to.shared.u64 t, %1; cvt.u32.u64 %0, t; }" : "=r"(a) : "l"(p));
    return a;
}
__device__ __forceinline__ void cp_async16(uint32_t dst, const void* src) {
    asm volatile("cp.async.cg.shared.global [%0], [%1], 16;" :: "r"(dst), "l"(src) : "memory");
}
__device__ __forceinline__ void cp_commit() {
    asm volatile("cp.async.commit_group;" ::: "memory");
}
template <int N>
__device__ __forceinline__ void cp_wait() {
    asm volatile("cp.async.wait_group %0;" :: "n"(N) : "memory");
}
__device__ __forceinline__ void ldsm_x4(uint32_t* r, uint32_t addr) {
    asm volatile("ldmatrix.sync.aligned.m8n8.x4.shared.b16 {%0,%1,%2,%3}, [%4];"
                 : "=r"(r[0]), "=r"(r[1]), "=r"(r[2]), "=r"(r[3]) : "r"(addr));
}
__device__ __forceinline__ void mma16816(float* d, const uint32_t* a, uint32_t b0, uint32_t b1) {
    asm volatile("mma.sync.aligned.m16n8k16.row.col.f32.bf16.bf16.f32 "
                 "{%0,%1,%2,%3}, {%4,%5,%6,%7}, {%8,%9}, {%0,%1,%2,%3};"
                 : "+f"(d[0]), "+f"(d[1]), "+f"(d[2]), "+f"(d[3])
                 : "r"(a[0]), "r"(a[1]), "r"(a[2]), "r"(a[3]), "r"(b0), "r"(b1));
}

// ---------------- zero accumulators (must run every graph replay) ----------------
__global__ void zero_kernel() {
    int i = blockIdx.x * blockDim.x + threadIdx.x;
    if (i < NB * NHEADS * HD * HD) g_kv[i] = 0.f;
    if (i < NB * NHEADS * HD) { g_km[i] = 0.f; g_qm[i] = 0.f; }
}

// ---------------- weight convert: fp32 -> bf16 hi/lo ----------------
__global__ void wconv_kernel(const float* __restrict__ w, __nv_bfloat16* __restrict__ wh,
                             __nv_bfloat16* __restrict__ wl, int n)
{
    int i = blockIdx.x * 256 + threadIdx.x;
    if (i < n) {
        float v = w[i];
        __nv_bfloat16 h = __float2bfloat16(v);
        wh[i] = h;
        wl[i] = __float2bfloat16(v - __bfloat162float(h));
    }
}

// ---------------- transpose-convert: x[b][k][n] fp32 -> xT[b][n][k] bf16 hi/lo ----------------
__global__ void __launch_bounds__(256) xpose_kernel(const float* __restrict__ x)
{
    const int b = blockIdx.z;
    const float* src = x + (size_t)b * 512 * NT;
    __nv_bfloat16* dh = g_xth + (size_t)b * NT * 512;
    __nv_bfloat16* dl = g_xtl + (size_t)b * NT * 512;
    __shared__ float tile[32][33];
    const int n0 = blockIdx.x * 32, k0 = blockIdx.y * 32;
    const int tx = threadIdx.x & 31, ty = threadIdx.x >> 5; // 32x8
#pragma unroll
    for (int i = 0; i < 32; i += 8)
        tile[ty + i][tx] = src[(size_t)(k0 + ty + i) * NT + n0 + tx];
    __syncthreads();
#pragma unroll
    for (int i = 0; i < 32; i += 8) {
        float v = tile[tx][ty + i];
        __nv_bfloat16 h = __float2bfloat16(v);
        size_t o = (size_t)(n0 + ty + i) * 512 + k0 + tx;
        dh[o] = h;
        dl[o] = __float2bfloat16(v - __bfloat162float(h));
    }
}

// ---------------- HMMA GEMM: C[b][m][n] = sum_k A[m,k]*B[b][n,k] + bias[m] ----------------
// A,B bf16 hi/lo (3-product split). 128x128 CTA tile, BK=32, cp.async double buffer.
// SMEM rows padded to 40 elements (80B): stride 20 words mod 32 -> conflict-free ldmatrix.
#define SROW 40
#define ARR_BYTES (128 * SROW * 2)     // 10240
#define STAGE_BYTES (4 * ARR_BYTES)    // 40960
#define GEMM_SMEM (2 * STAGE_BYTES)    // 81920

__global__ void __launch_bounds__(256, 2) gemm_hmma_kernel(
    const __nv_bfloat16* __restrict__ Ah, const __nv_bfloat16* __restrict__ Al,
    const __nv_bfloat16* __restrict__ Bh, const __nv_bfloat16* __restrict__ Bl,
    const float* __restrict__ bias, float* __restrict__ C, int M, int N)
{
    const int b = blockIdx.z;
    const int m0 = blockIdx.y * 128, n0 = blockIdx.x * 128;
    const __nv_bfloat16* pAh = Ah + (size_t)m0 * 512;
    const __nv_bfloat16* pAl = Al + (size_t)m0 * 512;
    const __nv_bfloat16* pBh = Bh + ((size_t)b * N + n0) * 512;
    const __nv_bfloat16* pBl = Bl + ((size_t)b * N + n0) * 512;
    float* Cb = C + (size_t)b * M * N;

    extern __shared__ char smem[];
    const uint32_t sb = smem_u32(smem);

    const int tid = threadIdx.x;
    const int lane = tid & 31, wid = tid >> 5;
    const int warp_m = wid & 3, warp_n = wid >> 2;   // 4 x 2 warps -> 32 x 64 per warp

    // cp.async mapping: thread -> (row, half)
    const int lrow = tid >> 1, lhalf = tid & 1;
    const size_t goff = (size_t)lrow * 512 + lhalf * 16;   // elements
    const uint32_t soff = (uint32_t)(lrow * SROW + lhalf * 16) * 2; // bytes

    // ldmatrix per-lane offsets (A and B both non-trans: SMEM is [row][k])
    const int arow = ((lane >> 3) & 1) * 8 + (lane & 7);   // = lane % 16
    const int acol = (lane >> 4) * 8;                      // k element offset
    const int brow = ((lane >> 4) & 1) * 8 + (lane & 7);   // n row within 16
    const int bcol = ((lane >> 3) & 1) * 8;                // k element offset

    float acc[2][8][4];
#pragma unroll
    for (int i = 0; i < 2; i++)
#pragma unroll
        for (int j = 0; j < 8; j++)
#pragma unroll
            for (int q = 0; q < 4; q++) acc[i][j][q] = 0.f;

    // issue stage 0
    {
        uint32_t d = sb + soff;
        cp_async16(d + 0 * ARR_BYTES, pAh + goff);
        cp_async16(d + 0 * ARR_BYTES + 16, pAh + goff + 8);
        cp_async16(d + 1 * ARR_BYTES, pAl + goff);
        cp_async16(d + 1 * ARR_BYTES + 16, pAl + goff + 8);
        cp_async16(d + 2 * ARR_BYTES, pBh + goff);
        cp_async16(d + 2 * ARR_BYTES + 16, pBh + goff + 8);
        cp_async16(d + 3 * ARR_BYTES, pBl + goff);
        cp_async16(d + 3 * ARR_BYTES + 16, pBl + goff + 8);
        cp_commit();
    }

    for (int c = 0; c < 16; c++) {
        if (c + 1 < 16) {
            const size_t g = goff + (c + 1) * 32;
            uint32_t d = sb + ((c + 1) & 1) * STAGE_BYTES + soff;
            cp_async16(d + 0 * ARR_BYTES, pAh + g);
            cp_async16(d + 0 * ARR_BYTES + 16, pAh + g + 8);
            cp_async16(d + 1 * ARR_BYTES, pAl + g);
            cp_async16(d + 1 * ARR_BYTES + 16, pAl + g + 8);
            cp_async16(d + 2 * ARR_BYTES, pBh + g);
            cp_async16(d + 2 * ARR_BYTES + 16, pBh + g + 8);
            cp_async16(d + 3 * ARR_BYTES, pBl + g);
            cp_async16(d + 3 * ARR_BYTES + 16, pBl + g + 8);
            cp_commit();
            cp_wait<1>();
        } else {
            cp_wait<0>();
        }
        __syncthreads();

        const uint32_t st = sb + (c & 1) * STAGE_BYTES;
        const uint32_t aBh = st + 0 * ARR_BYTES;  // Ah
        const uint32_t aBl = st + 1 * ARR_BYTES;  // Al
        const uint32_t bBh = st + 2 * ARR_BYTES;  // Bh
        const uint32_t bBl = st + 3 * ARR_BYTES;  // Bl

#pragma unroll
        for (int kk = 0; kk < 2; kk++) {
            uint32_t ah[2][4], al[2][4];
#pragma unroll
            for (int mt = 0; mt < 2; mt++) {
                uint32_t ao = (uint32_t)((warp_m * 32 + mt * 16 + arow) * SROW + kk * 16 + acol) * 2;
                ldsm_x4(ah[mt], aBh + ao);
                ldsm_x4(al[mt], aBl + ao);
            }
#pragma unroll
            for (int g = 0; g < 4; g++) {
                uint32_t bo = (uint32_t)((warp_n * 64 + g * 16 + brow) * SROW + kk * 16 + bcol) * 2;
                uint32_t bh[4], bl[4];
                ldsm_x4(bh, bBh + bo);   // non-trans: SMEM already [n][k] (col-major B)
                ldsm_x4(bl, bBl + bo);
#pragma unroll
                for (int mt = 0; mt < 2; mt++) {
                    mma16816(acc[mt][g * 2 + 0], ah[mt], bh[0], bh[1]);
                    mma16816(acc[mt][g * 2 + 1], ah[mt], bh[2], bh[3]);
                    mma16816(acc[mt][g * 2 + 0], ah[mt], bl[0], bl[1]);
                    mma16816(acc[mt][g * 2 + 1], ah[mt], bl[2], bl[3]);
                    mma16816(acc[mt][g * 2 + 0], al[mt], bh[0], bh[1]);
                    mma16816(acc[mt][g * 2 + 1], al[mt], bh[2], bh[3]);
                }
            }
        }
        __syncthreads();
    }

    // epilogue: direct float2 stores + bias
#pragma unroll
    for (int mt = 0; mt < 2; mt++) {
        int mA = m0 + warp_m * 32 + mt * 16 + (lane >> 2);
        float bv0 = bias[mA], bv1 = bias[mA + 8];
        float* row0 = Cb + (size_t)mA * N;
        float* row1 = row0 + (size_t)8 * N;
#pragma unroll
        for (int nt = 0; nt < 8; nt++) {
            int n = n0 + warp_n * 64 + nt * 8 + (lane & 3) * 2;
            float2 v0 = make_float2(acc[mt][nt][0] + bv0, acc[mt][nt][1] + bv0);
            float2 v1 = make_float2(acc[mt][nt][2] + bv1, acc[mt][nt][3] + bv1);
            *(float2*)(row0 + n) = v0;
            *(float2*)(row1 + n) = v1;
        }
    }
}

// ---------------- depthwise 5x5 conv on v channels -> g_lepe ----------------
__global__ void __launch_bounds__(256) conv_kernel(
    const float* __restrict__ w_lepe, const float* __restrict__ b_lepe)
{
    const int bc = blockIdx.x;
    const int b = bc >> 9, c = bc & 511;
    __shared__ float wsh[25];
    const int tid = threadIdx.x;
    if (tid < 25) wsh[tid] = w_lepe[c * 25 + tid];
    __syncthreads();

    const int y = blockIdx.y * 4 + (tid >> 6);
    const int xw = tid & 63;
    const float* Vp = g_qkvo + ((size_t)b * 2048 + 1024 + c) * NT;

    float acc = b_lepe[c];
#pragma unroll
    for (int i = 0; i < 5; i++) {
        int yy = y + i - 2;
        if (yy < 0 || yy >= 64) continue;
#pragma unroll
        for (int j = 0; j < 5; j++) {
            int xx = xw + j - 2;
            if (xx < 0 || xx >= 64) continue;
            acc += wsh[i * 5 + j] * Vp[yy * 64 + xx];
        }
    }
    g_lepe[((size_t)b * 512 + c) * NT + y * 64 + xw] = acc;
}

// ---------------- split stats: qmean -> logits -> softmax ----------------
__global__ void __launch_bounds__(256) qmean_kernel()
{
    const int bh = blockIdx.x;
    const int b = bh >> 3, h = bh & 7;
    const float* Q = g_qkvo + ((size_t)b * 2048 + h * 64) * NT;
    __shared__ float s[64];
    const int tid = threadIdx.x, lane = tid & 31;
    if (tid < 64) s[tid] = 0.f;
    __syncthreads();
    const int t0 = blockIdx.y * 512;
    for (int d = 0; d < 64; d++) {
        float p = elu1(Q[(size_t)d * NT + t0 + tid]) + elu1(Q[(size_t)d * NT + t0 + 256 + tid]);
        p = warpSum(p);
        if (lane == 0) atomicAdd(&s[d], p);
    }
    __syncthreads();
    if (tid < 64) atomicAdd(&g_qm[bh * 64 + tid], s[tid]);
}

__global__ void __launch_bounds__(256) logits_kernel()
{
    const int bh = blockIdx.x;
    const int b = bh >> 3, h = bh & 7;
    const float* Kp = g_qkvo + ((size_t)b * 2048 + 512 + h * 64) * NT;
    __shared__ float sq[64];
    const int tid = threadIdx.x;
    if (tid < 64) sq[tid] = g_qm[bh * 64 + tid] * (1.f / NT);
    __syncthreads();
    const int t = blockIdx.y * 256 + tid;
    float l = 0.f;
#pragma unroll 8
    for (int d = 0; d < 64; d++) l += sq[d] * elu1(Kp[(size_t)d * NT + t]);
    g_eff[bh * NT + t] = l * 0.125f;   // SCALE
}

__global__ void __launch_bounds__(256) softmax_kernel()
{
    const int bh = blockIdx.x;
    const int tid = threadIdx.x;
    const int lane = tid & 31, wid = tid >> 5;
    __shared__ float red[8];
    float l[16];
#pragma unroll
    for (int i = 0; i < 16; i++) l[i] = g_eff[bh * NT + tid + i * 256];
    float mx = -1e30f;
#pragma unroll
    for (int i = 0; i < 16; i++) mx = fmaxf(mx, l[i]);
    mx = warpMax(mx);
    if (lane == 0) red[wid] = mx;
    __syncthreads();
    if (tid == 0) { float m = red[0]; for (int w = 1; w < 8; w++) m = fmaxf(m, red[w]); red[0] = m; }
    __syncthreads();
    mx = red[0];
    __syncthreads();
    float s = 0.f;
#pragma unroll
    for (int i = 0; i < 16; i++) s += __expf(l[i] - mx);
    s = warpSum(s);
    if (lane == 0) red[wid] = s;
    __syncthreads();
    if (tid == 0) { float ss = 0.f; for (int w = 0; w < 8; w++) ss += red[w]; red[0] = ss; }
    __syncthreads();
    const float inv = 1.f / red[0];
#pragma unroll
    for (int i = 0; i < 16; i++)
        g_eff[bh * NT + tid + i * 256] = __expf(l[i] - mx) * inv;
}

// ---------------- kv[d,e] = sum_t rope(k*eff)[t,d]*v[t,e];  km[d] = sum_t k*eff ----------------
__global__ void __launch_bounds__(256) kv_kernel(
    const float* __restrict__ sinp, const float* __restrict__ cosp)
{
    const int bh = blockIdx.x;
    const int b = bh >> 3, h = bh & 7;
    const int chunk = blockIdx.y;   // 16 chunks of 256 t
    const float* Kp  = g_qkvo + ((size_t)b * 2048 +  512 + h * 64) * NT;
    const float* Vp  = g_qkvo + ((size_t)b * 2048 + 1024 + h * 64) * NT;
    const float* eff = g_eff + bh * NT;

    __shared__ float sk[64][65];
    __shared__ float sv[64][65];

    const int tid = threadIdx.x;
    const int ttl = tid & 63;
    const int drow = tid >> 6;
    const int d0 = (tid & 15) * 4, e0 = (tid >> 4) * 4;

    float acc[4][4];
#pragma unroll
    for (int i = 0; i < 4; i++)
#pragma unroll
        for (int j = 0; j < 4; j++) acc[i][j] = 0.f;
    float kmacc = 0.f;

    for (int tile = 0; tile < 4; tile++) {
        const int t0 = chunk * 256 + tile * 64;
        const float effv = eff[t0 + ttl];
#pragma unroll
        for (int r = 0; r < 16; r++) {
            int d = drow + r * 4;
            sk[ttl][d] = elu1(Kp[(size_t)d * NT + t0 + ttl]) * effv;
            sv[ttl][d] = Vp[(size_t)d * NT + t0 + ttl];
        }
        __syncthreads();

        if (tid < 64) {
#pragma unroll 8
            for (int tt = 0; tt < 64; tt++) kmacc += sk[tt][tid];
        }
        float r0[8], r1[8];
        const int t = t0 + ttl;
#pragma unroll
        for (int r = 0; r < 8; r++) {
            int pr = drow + r * 4;
            int d = 2 * pr;
            float a  = sk[ttl][d];
            float bb = sk[ttl][d + 1];
            float c0 = cosp[t * 64 + d],     s0 = sinp[t * 64 + d];
            float c1 = cosp[t * 64 + d + 1], s1 = sinp[t * 64 + d + 1];
            r0[r] = a * c0 - bb * s0;
            r1[r] = bb * c1 + a * s1;
        }
        __syncthreads();
#pragma unroll
        for (int r = 0; r < 8; r++) {
            int d = 2 * (drow + r * 4);
            sk[ttl][d]     = r0[r];
            sk[ttl][d + 1] = r1[r];
        }
        __syncthreads();

#pragma unroll 4
        for (int tt = 0; tt < 64; tt++) {
            float kk[4], vv[4];
#pragma unroll
            for (int j = 0; j < 4; j++) { kk[j] = sk[tt][d0 + j]; vv[j] = sv[tt][e0 + j]; }
#pragma unroll
            for (int i = 0; i < 4; i++)
#pragma unroll
                for (int j = 0; j < 4; j++) acc[i][j] += kk[i] * vv[j];
        }
        __syncthreads();
    }

    float* kvout = g_kv + (size_t)bh * HD * HD;
#pragma unroll
    for (int i = 0; i < 4; i++)
#pragma unroll
        for (int j = 0; j < 4; j++)
            atomicAdd(&kvout[(d0 + i) * 64 + e0 + j], acc[i][j]);
    if (tid < 64) atomicAdd(&g_km[bh * 64 + tid], kmacc);
}

// ---------------- res: y = (attn*z + lepe)*gate -> yT bf16 hi/lo ----------------
__global__ void __launch_bounds__(256) res_kernel(
    const float* __restrict__ sinp, const float* __restrict__ cosp)
{
    const int bh = blockIdx.x;
    const int b = bh >> 3, h = bh & 7;
    const int tid = threadIdx.x;
    const int t = blockIdx.y * 256 + tid;
    const float* Q = g_qkvo + ((size_t)b * 2048 + h * 64) * NT;

    __shared__ float skv[64][64];
    __shared__ float skm[64];
#pragma unroll
    for (int r = 0; r < 16; r++)
        ((float*)skv)[tid + r * 256] = g_kv[(size_t)bh * 4096 + tid + r * 256];
    if (tid < 64) skm[tid] = g_km[bh * 64 + tid];
    __syncthreads();

    float res[64];
#pragma unroll
    for (int e = 0; e < 64; e++) res[e] = 0.f;
    float zacc = 0.f;

    for (int p = 0; p < 32; p++) {
        const int d = 2 * p;
        float q0 = elu1(Q[(size_t)d * NT + t]);
        float q1 = elu1(Q[(size_t)(d + 1) * NT + t]);
        zacc += q0 * skm[d] + q1 * skm[d + 1];
        float c0 = cosp[t * 64 + d],     s0 = sinp[t * 64 + d];
        float c1 = cosp[t * 64 + d + 1], s1 = sinp[t * 64 + d + 1];
        float qr0 = q0 * c0 - q1 * s0;
        float qr1 = q1 * c1 + q0 * s1;
        const float4* kv0 = (const float4*)skv[d];
        const float4* kv1 = (const float4*)skv[d + 1];
#pragma unroll
        for (int e4 = 0; e4 < 16; e4++) {
            float4 a = kv0[e4], bb = kv1[e4];
            res[e4 * 4 + 0] += qr0 * a.x + qr1 * bb.x;
            res[e4 * 4 + 1] += qr0 * a.y + qr1 * bb.y;
            res[e4 * 4 + 2] += qr0 * a.z + qr1 * bb.z;
            res[e4 * 4 + 3] += qr0 * a.w + qr1 * bb.w;
        }
    }
    const float z = 1.f / (zacc + 1e-6f);

    const size_t yrow = ((size_t)b * NT + t) * 512 + h * 64;
#pragma unroll 8
    for (int e = 0; e < 64; e++) {
        int c = h * 64 + e;
        size_t idx = ((size_t)b * 512 + c) * NT + t;
        float gate = g_qkvo[((size_t)b * 2048 + 1536 + c) * NT + t];
        float yv = (res[e] * z + g_lepe[idx]) * gate;
        __nv_bfloat16 hh = __float2bfloat16(yv);
        g_yth[yrow + e] = hh;
        g_ytl[yrow + e] = __float2bfloat16(yv - __bfloat162float(hh));
    }
}

// ---------------- launch ----------------
extern "C" void kernel_launch(void* const* d_in, const int* in_sizes, int n_in,
                              void* d_out, int out_size)
{
    const float* x      = (const float*)d_in[0];
    const float* sinp   = (const float*)d_in[1];
    const float* cosp   = (const float*)d_in[2];
    const float* w_qkvo = (const float*)d_in[3];
    const float* b_qkvo = (const float*)d_in[4];
    const float* w_lepe = (const float*)d_in[5];
    const float* b_lepe = (const float*)d_in[6];
    const float* w_proj = (const float*)d_in[7];
    const float* b_proj = (const float*)d_in[8];
    float* out = (float*)d_out;

    float* qkvo_p = nullptr;
    __nv_bfloat16 *wqh, *wql, *wph, *wpl, *xth, *xtl, *yth, *ytl;
    cudaGetSymbolAddress((void**)&qkvo_p, g_qkvo);
    cudaGetSymbolAddress((void**)&wqh, g_wqh);
    cudaGetSymbolAddress((void**)&wql, g_wql);
    cudaGetSymbolAddress((void**)&wph, g_wph);
    cudaGetSymbolAddress((void**)&wpl, g_wpl);
    cudaGetSymbolAddress((void**)&xth, g_xth);
    cudaGetSymbolAddress((void**)&xtl, g_xtl);
    cudaGetSymbolAddress((void**)&yth, g_yth);
    cudaGetSymbolAddress((void**)&ytl, g_ytl);

    cudaFuncSetAttribute(gemm_hmma_kernel, cudaFuncAttributeMaxDynamicSharedMemorySize, GEMM_SMEM);

    zero_kernel<<<(NB * NHEADS * HD * HD + 255) / 256, 256>>>();

    wconv_kernel<<<(2048 * 512 + 255) / 256, 256>>>(w_qkvo, wqh, wql, 2048 * 512);
    wconv_kernel<<<(512 * 512 + 255) / 256, 256>>>(w_proj, wph, wpl, 512 * 512);
    xpose_kernel<<<dim3(NT / 32, 512 / 32, NB), 256>>>(x);

    // GEMM1: qkvo[b][2048][4096]
    gemm_hmma_kernel<<<dim3(NT / 128, 2048 / 128, NB), 256, GEMM_SMEM>>>(
        wqh, wql, xth, xtl, b_qkvo, qkvo_p, 2048, NT);

    conv_kernel<<<dim3(NB * CDIM, 16), 256>>>(w_lepe, b_lepe);

    qmean_kernel<<<dim3(NB * NHEADS, 8), 256>>>();
    logits_kernel<<<dim3(NB * NHEADS, 16), 256>>>();
    softmax_kernel<<<NB * NHEADS, 256>>>();

    kv_kernel<<<dim3(NB * NHEADS, 16), 256>>>(sinp, cosp);
    res_kernel<<<dim3(NB * NHEADS, 16), 256>>>(sinp, cosp);

    // GEMM2: out[b][512][4096]
    gemm_hmma_kernel<<<dim3(NT / 128, 512 / 128, NB), 256, GEMM_SMEM>>>(
        wph, wpl, yth, ytl, b_proj, out, 512, NT);
}

// round 7
// speedup vs baseline: 1.9742x; 1.1947x over previous
#include <cuda_runtime.h>
#include <cuda_fp16.h>
#include <cstdint>

#define NB 8
#define CDIM 512
#define NHEADS 8
#define HD 64
#define NT 4096           // H*W = 64*64

// ---------------- scratch (device globals: alloc-free) ----------------
__device__ float g_qkvo[(size_t)NB * 2048 * NT];   // 268 MB fp32 qkvo
__device__ float g_lepe[(size_t)NB * CDIM * NT];   // 67 MB
__device__ float g_eff [NB * NHEADS * NT];
__device__ float g_kv  [NB * NHEADS * HD * HD];
__device__ float g_km  [NB * NHEADS * HD];
__device__ float g_qm  [NB * NHEADS * HD];

// fp16 operand buffers for tensor-core GEMMs (weights hi-only; activations hi+lo)
__device__ __half g_wqh[2048 * 512];
__device__ __half g_wph[512 * 512];
__device__ __half g_xth[(size_t)NB * NT * 512], g_xtl[(size_t)NB * NT * 512];
__device__ __half g_yth[(size_t)NB * NT * 512], g_ytl[(size_t)NB * NT * 512];

__device__ __forceinline__ float elu1(float x) { return x > 0.f ? x + 1.f : __expf(x); }

__device__ __forceinline__ float warpSum(float v) {
#pragma unroll
    for (int o = 16; o > 0; o >>= 1) v += __shfl_xor_sync(0xffffffffu, v, o);
    return v;
}
__device__ __forceinline__ float warpMax(float v) {
#pragma unroll
    for (int o = 16; o > 0; o >>= 1) v = fmaxf(v, __shfl_xor_sync(0xffffffffu, v, o));
    return v;
}

__device__ __forceinline__ uint32_t smem_u32(const void* p) {
    uint32_t a;
    asm("{ .reg .u64 t; cvta.to.shared.u64 t, %1; cvt.u32.u64 %0, t; }" : "=r"(a) : "l"(p));
    return a;
}
__device__ __forceinline__ void cp_async16(uint32_t dst, const void* src) {
    asm volatile("cp.async.cg.shared.global [%0], [%1], 16;" :: "r"(dst), "l"(src) : "memory");
}
__device__ __forceinline__ void cp_commit() {
    asm volatile("cp.async.commit_group;" ::: "memory");
}
template <int N>
__device__ __forceinline__ void cp_wait() {
    asm volatile("cp.async.wait_group %0;" :: "n"(N) : "memory");
}
__device__ __forceinline__ void ldsm_x4(uint32_t* r, uint32_t addr) {
    asm volatile("ldmatrix.sync.aligned.m8n8.x4.shared.b16 {%0,%1,%2,%3}, [%4];"
                 : "=r"(r[0]), "=r"(r[1]), "=r"(r[2]), "=r"(r[3]) : "r"(addr));
}
__device__ __forceinline__ void mma16816(float* d, const uint32_t* a, uint32_t b0, uint32_t b1) {
    asm volatile("mma.sync.aligned.m16n8k16.row.col.f32.f16.f16.f32 "
                 "{%0,%1,%2,%3}, {%4,%5,%6,%7}, {%8,%9}, {%0,%1,%2,%3};"
                 : "+f"(d[0]), "+f"(d[1]), "+f"(d[2]), "+f"(d[3])
                 : "r"(a[0]), "r"(a[1]), "r"(a[2]), "r"(a[3]), "r"(b0), "r"(b1));
}

// ---------------- zero accumulators (must run every graph replay) ----------------
__global__ void zero_kernel() {
    int i = blockIdx.x * blockDim.x + threadIdx.x;
    if (i < NB * NHEADS * HD * HD) g_kv[i] = 0.f;
    if (i < NB * NHEADS * HD) { g_km[i] = 0.f; g_qm[i] = 0.f; }
}

// ---------------- weight convert: fp32 -> fp16 (hi only) ----------------
__global__ void wconv_kernel(const float* __restrict__ w, __half* __restrict__ wh, int n)
{
    int i = blockIdx.x * 256 + threadIdx.x;
    if (i < n) wh[i] = __float2half(w[i]);
}

// ---------------- transpose-convert: x[b][k][n] fp32 -> xT[b][n][k] fp16 hi/lo ----------------
__global__ void __launch_bounds__(256) xpose_kernel(const float* __restrict__ x)
{
    const int b = blockIdx.z;
    const float* src = x + (size_t)b * 512 * NT;
    __half* dh = g_xth + (size_t)b * NT * 512;
    __half* dl = g_xtl + (size_t)b * NT * 512;
    __shared__ float tile[32][33];
    const int n0 = blockIdx.x * 32, k0 = blockIdx.y * 32;
    const int tx = threadIdx.x & 31, ty = threadIdx.x >> 5; // 32x8
#pragma unroll
    for (int i = 0; i < 32; i += 8)
        tile[ty + i][tx] = src[(size_t)(k0 + ty + i) * NT + n0 + tx];
    __syncthreads();
#pragma unroll
    for (int i = 0; i < 32; i += 8) {
        float v = tile[tx][ty + i];
        __half h = __float2half(v);
        size_t o = (size_t)(n0 + ty + i) * 512 + k0 + tx;
        dh[o] = h;
        dl[o] = __float2half(v - __half2float(h));
    }
}

// ---------------- HMMA GEMM: C[b][m][n] = sum_k A[m,k]*B[b][n,k] + bias[m] ----------------
// A fp16 hi-only; B fp16 hi+lo (2-product split). 128x128 CTA tile, BK=32,
// cp.async double buffer, ONE barrier per k-chunk (wait -> bar -> issue -> compute).
// SMEM rows padded to 40 halfs (80B): stride 20 words mod 32 -> conflict-free ldmatrix.
#define SROW 40
#define ARR_BYTES (128 * SROW * 2)     // 10240
#define STAGE_BYTES (3 * ARR_BYTES)    // 30720
#define GEMM_SMEM (2 * STAGE_BYTES)    // 61440

__global__ void __launch_bounds__(256, 2) gemm_hmma_kernel(
    const __half* __restrict__ Ah,
    const __half* __restrict__ Bh, const __half* __restrict__ Bl,
    const float* __restrict__ bias, float* __restrict__ C, int M, int N)
{
    const int b = blockIdx.z;
    const int m0 = blockIdx.y * 128, n0 = blockIdx.x * 128;
    const __half* pAh = Ah + (size_t)m0 * 512;
    const __half* pBh = Bh + ((size_t)b * N + n0) * 512;
    const __half* pBl = Bl + ((size_t)b * N + n0) * 512;
    float* Cb = C + (size_t)b * M * N;

    extern __shared__ char smem[];
    const uint32_t sb = smem_u32(smem);

    const int tid = threadIdx.x;
    const int lane = tid & 31, wid = tid >> 5;
    const int warp_m = wid & 3, warp_n = wid >> 2;   // 4 x 2 warps -> 32 x 64 per warp

    // cp.async mapping: thread -> (row, half)
    const int lrow = tid >> 1, lhalf = tid & 1;
    const size_t goff = (size_t)lrow * 512 + lhalf * 16;            // elements
    const uint32_t soff = (uint32_t)(lrow * SROW + lhalf * 16) * 2; // bytes

    // ldmatrix per-lane offsets (A and B both non-trans: SMEM is [row][k])
    const int arow = ((lane >> 3) & 1) * 8 + (lane & 7);   // = lane % 16
    const int acol = (lane >> 4) * 8;                      // k element offset
    const int brow = ((lane >> 4) & 1) * 8 + (lane & 7);   // n row within 16
    const int bcol = ((lane >> 3) & 1) * 8;                // k element offset

    float acc[2][8][4];
#pragma unroll
    for (int i = 0; i < 2; i++)
#pragma unroll
        for (int j = 0; j < 8; j++)
#pragma unroll
            for (int q = 0; q < 4; q++) acc[i][j][q] = 0.f;

    // prologue: stage 0
    {
        uint32_t d = sb + soff;
        cp_async16(d + 0 * ARR_BYTES, pAh + goff);
        cp_async16(d + 0 * ARR_BYTES + 16, pAh + goff + 8);
        cp_async16(d + 1 * ARR_BYTES, pBh + goff);
        cp_async16(d + 1 * ARR_BYTES + 16, pBh + goff + 8);
        cp_async16(d + 2 * ARR_BYTES, pBl + goff);
        cp_async16(d + 2 * ARR_BYTES + 16, pBl + goff + 8);
        cp_commit();
    }

    for (int c = 0; c < 16; c++) {
        cp_wait<0>();
        __syncthreads();

        if (c + 1 < 16) {     // issue next chunk into the other stage (consumed @ c-1)
            const size_t g = goff + (c + 1) * 32;
            uint32_t d = sb + ((c + 1) & 1) * STAGE_BYTES + soff;
            cp_async16(d + 0 * ARR_BYTES, pAh + g);
            cp_async16(d + 0 * ARR_BYTES + 16, pAh + g + 8);
            cp_async16(d + 1 * ARR_BYTES, pBh + g);
            cp_async16(d + 1 * ARR_BYTES + 16, pBh + g + 8);
            cp_async16(d + 2 * ARR_BYTES, pBl + g);
            cp_async16(d + 2 * ARR_BYTES + 16, pBl + g + 8);
            cp_commit();
        }

        const uint32_t st = sb + (c & 1) * STAGE_BYTES;
        const uint32_t aB  = st + 0 * ARR_BYTES;  // A hi
        const uint32_t bBh = st + 1 * ARR_BYTES;  // B hi
        const uint32_t bBl = st + 2 * ARR_BYTES;  // B lo

#pragma unroll
        for (int kk = 0; kk < 2; kk++) {
            uint32_t ah[2][4];
#pragma unroll
            for (int mt = 0; mt < 2; mt++) {
                uint32_t ao = (uint32_t)((warp_m * 32 + mt * 16 + arow) * SROW + kk * 16 + acol) * 2;
                ldsm_x4(ah[mt], aB + ao);
            }
#pragma unroll
            for (int g = 0; g < 4; g++) {
                uint32_t bo = (uint32_t)((warp_n * 64 + g * 16 + brow) * SROW + kk * 16 + bcol) * 2;
                uint32_t bh[4], bl[4];
                ldsm_x4(bh, bBh + bo);   // non-trans: SMEM already [n][k] (col-major B)
                ldsm_x4(bl, bBl + bo);
#pragma unroll
                for (int mt = 0; mt < 2; mt++) {
                    mma16816(acc[mt][g * 2 + 0], ah[mt], bh[0], bh[1]);
                    mma16816(acc[mt][g * 2 + 1], ah[mt], bh[2], bh[3]);
                    mma16816(acc[mt][g * 2 + 0], ah[mt], bl[0], bl[1]);
                    mma16816(acc[mt][g * 2 + 1], ah[mt], bl[2], bl[3]);
                }
            }
        }
        __syncthreads();   // protect stage (c&1) before it is re-filled at c+1
    }

    // epilogue: direct float2 stores + bias
#pragma unroll
    for (int mt = 0; mt < 2; mt++) {
        int mA = m0 + warp_m * 32 + mt * 16 + (lane >> 2);
        float bv0 = bias[mA], bv1 = bias[mA + 8];
        float* row0 = Cb + (size_t)mA * N;
        float* row1 = row0 + (size_t)8 * N;
#pragma unroll
        for (int nt = 0; nt < 8; nt++) {
            int n = n0 + warp_n * 64 + nt * 8 + (lane & 3) * 2;
            float2 v0 = make_float2(acc[mt][nt][0] + bv0, acc[mt][nt][1] + bv0);
            float2 v1 = make_float2(acc[mt][nt][2] + bv1, acc[mt][nt][3] + bv1);
            *(float2*)(row0 + n) = v0;
            *(float2*)(row1 + n) = v1;
        }
    }
}

// ---------------- depthwise 5x5 conv on v channels -> g_lepe ----------------
__global__ void __launch_bounds__(256) conv_kernel(
    const float* __restrict__ w_lepe, const float* __restrict__ b_lepe)
{
    const int bc = blockIdx.x;
    const int b = bc >> 9, c = bc & 511;
    __shared__ float wsh[25];
    const int tid = threadIdx.x;
    if (tid < 25) wsh[tid] = w_lepe[c * 25 + tid];
    __syncthreads();

    const int y = blockIdx.y * 4 + (tid >> 6);
    const int xw = tid & 63;
    const float* Vp = g_qkvo + ((size_t)b * 2048 + 1024 + c) * NT;

    float acc = b_lepe[c];
#pragma unroll
    for (int i = 0; i < 5; i++) {
        int yy = y + i - 2;
        if (yy < 0 || yy >= 64) continue;
#pragma unroll
        for (int j = 0; j < 5; j++) {
            int xx = xw + j - 2;
            if (xx < 0 || xx >= 64) continue;
            acc += wsh[i * 5 + j] * Vp[yy * 64 + xx];
        }
    }
    g_lepe[((size_t)b * 512 + c) * NT + y * 64 + xw] = acc;
}

// ---------------- split stats: qmean -> logits -> softmax ----------------
__global__ void __launch_bounds__(256) qmean_kernel()
{
    const int bh = blockIdx.x;
    const int b = bh >> 3, h = bh & 7;
    const float* Q = g_qkvo + ((size_t)b * 2048 + h * 64) * NT;
    __shared__ float s[64];
    const int tid = threadIdx.x, lane = tid & 31;
    if (tid < 64) s[tid] = 0.f;
    __syncthreads();
    const int t0 = blockIdx.y * 512;
    for (int d = 0; d < 64; d++) {
        float p = elu1(Q[(size_t)d * NT + t0 + tid]) + elu1(Q[(size_t)d * NT + t0 + 256 + tid]);
        p = warpSum(p);
        if (lane == 0) atomicAdd(&s[d], p);
    }
    __syncthreads();
    if (tid < 64) atomicAdd(&g_qm[bh * 64 + tid], s[tid]);
}

__global__ void __launch_bounds__(256) logits_kernel()
{
    const int bh = blockIdx.x;
    const int b = bh >> 3, h = bh & 7;
    const float* Kp = g_qkvo + ((size_t)b * 2048 + 512 + h * 64) * NT;
    __shared__ float sq[64];
    const int tid = threadIdx.x;
    if (tid < 64) sq[tid] = g_qm[bh * 64 + tid] * (1.f / NT);
    __syncthreads();
    const int t = blockIdx.y * 256 + tid;
    float l = 0.f;
#pragma unroll 8
    for (int d = 0; d < 64; d++) l += sq[d] * elu1(Kp[(size_t)d * NT + t]);
    g_eff[bh * NT + t] = l * 0.125f;   // SCALE
}

__global__ void __launch_bounds__(256) softmax_kernel()
{
    const int bh = blockIdx.x;
    const int tid = threadIdx.x;
    const int lane = tid & 31, wid = tid >> 5;
    __shared__ float red[8];
    float l[16];
#pragma unroll
    for (int i = 0; i < 16; i++) l[i] = g_eff[bh * NT + tid + i * 256];
    float mx = -1e30f;
#pragma unroll
    for (int i = 0; i < 16; i++) mx = fmaxf(mx, l[i]);
    mx = warpMax(mx);
    if (lane == 0) red[wid] = mx;
    __syncthreads();
    if (tid == 0) { float m = red[0]; for (int w = 1; w < 8; w++) m = fmaxf(m, red[w]); red[0] = m; }
    __syncthreads();
    mx = red[0];
    __syncthreads();
    float s = 0.f;
#pragma unroll
    for (int i = 0; i < 16; i++) s += __expf(l[i] - mx);
    s = warpSum(s);
    if (lane == 0) red[wid] = s;
    __syncthreads();
    if (tid == 0) { float ss = 0.f; for (int w = 0; w < 8; w++) ss += red[w]; red[0] = ss; }
    __syncthreads();
    const float inv = 1.f / red[0];
#pragma unroll
    for (int i = 0; i < 16; i++)
        g_eff[bh * NT + tid + i * 256] = __expf(l[i] - mx) * inv;
}

// ---------------- kv[d,e] = sum_t rope(k*eff)[t,d]*v[t,e];  km[d] = sum_t k*eff ----------------
__global__ void __launch_bounds__(256) kv_kernel(
    const float* __restrict__ sinp, const float* __restrict__ cosp)
{
    const int bh = blockIdx.x;
    const int b = bh >> 3, h = bh & 7;
    const int chunk = blockIdx.y;   // 16 chunks of 256 t
    const float* Kp  = g_qkvo + ((size_t)b * 2048 +  512 + h * 64) * NT;
    const float* Vp  = g_qkvo + ((size_t)b * 2048 + 1024 + h * 64) * NT;
    const float* eff = g_eff + bh * NT;

    __shared__ float sk[64][65];
    __shared__ float sv[64][65];

    const int tid = threadIdx.x;
    const int ttl = tid & 63;
    const int drow = tid >> 6;
    const int d0 = (tid & 15) * 4, e0 = (tid >> 4) * 4;

    float acc[4][4];
#pragma unroll
    for (int i = 0; i < 4; i++)
#pragma unroll
        for (int j = 0; j < 4; j++) acc[i][j] = 0.f;
    float kmacc = 0.f;

    for (int tile = 0; tile < 4; tile++) {
        const int t0 = chunk * 256 + tile * 64;
        const float effv = eff[t0 + ttl];
#pragma unroll
        for (int r = 0; r < 16; r++) {
            int d = drow + r * 4;
            sk[ttl][d] = elu1(Kp[(size_t)d * NT + t0 + ttl]) * effv;
            sv[ttl][d] = Vp[(size_t)d * NT + t0 + ttl];
        }
        __syncthreads();

        if (tid < 64) {
#pragma unroll 8
            for (int tt = 0; tt < 64; tt++) kmacc += sk[tt][tid];
        }
        float r0[8], r1[8];
        const int t = t0 + ttl;
#pragma unroll
        for (int r = 0; r < 8; r++) {
            int pr = drow + r * 4;
            int d = 2 * pr;
            float a  = sk[ttl][d];
            float bb = sk[ttl][d + 1];
            float c0 = cosp[t * 64 + d],     s0 = sinp[t * 64 + d];
            float c1 = cosp[t * 64 + d + 1], s1 = sinp[t * 64 + d + 1];
            r0[r] = a * c0 - bb * s0;
            r1[r] = bb * c1 + a * s1;
        }
        __syncthreads();
#pragma unroll
        for (int r = 0; r < 8; r++) {
            int d = 2 * (drow + r * 4);
            sk[ttl][d]     = r0[r];
            sk[ttl][d + 1] = r1[r];
        }
        __syncthreads();

#pragma unroll 4
        for (int tt = 0; tt < 64; tt++) {
            float kk[4], vv[4];
#pragma unroll
            for (int j = 0; j < 4; j++) { kk[j] = sk[tt][d0 + j]; vv[j] = sv[tt][e0 + j]; }
#pragma unroll
            for (int i = 0; i < 4; i++)
#pragma unroll
                for (int j = 0; j < 4; j++) acc[i][j] += kk[i] * vv[j];
        }
        __syncthreads();
    }

    float* kvout = g_kv + (size_t)bh * HD * HD;
#pragma unroll
    for (int i = 0; i < 4; i++)
#pragma unroll
        for (int j = 0; j < 4; j++)
            atomicAdd(&kvout[(d0 + i) * 64 + e0 + j], acc[i][j]);
    if (tid < 64) atomicAdd(&g_km[bh * 64 + tid], kmacc);
}

// ---------------- res: y = (attn*z + lepe)*gate -> yT fp16 hi/lo ----------------
__global__ void __launch_bounds__(256) res_kernel(
    const float* __restrict__ sinp, const float* __restrict__ cosp)
{
    const int bh = blockIdx.x;
    const int b = bh >> 3, h = bh & 7;
    const int tid = threadIdx.x;
    const int t = blockIdx.y * 256 + tid;
    const float* Q = g_qkvo + ((size_t)b * 2048 + h * 64) * NT;

    __shared__ float skv[64][64];
    __shared__ float skm[64];
#pragma unroll
    for (int r = 0; r < 16; r++)
        ((float*)skv)[tid + r * 256] = g_kv[(size_t)bh * 4096 + tid + r * 256];
    if (tid < 64) skm[tid] = g_km[bh * 64 + tid];
    __syncthreads();

    float res[64];
#pragma unroll
    for (int e = 0; e < 64; e++) res[e] = 0.f;
    float zacc = 0.f;

    for (int p = 0; p < 32; p++) {
        const int d = 2 * p;
        float q0 = elu1(Q[(size_t)d * NT + t]);
        float q1 = elu1(Q[(size_t)(d + 1) * NT + t]);
        zacc += q0 * skm[d] + q1 * skm[d + 1];
        float c0 = cosp[t * 64 + d],     s0 = sinp[t * 64 + d];
        float c1 = cosp[t * 64 + d + 1], s1 = sinp[t * 64 + d + 1];
        float qr0 = q0 * c0 - q1 * s0;
        float qr1 = q1 * c1 + q0 * s1;
        const float4* kv0 = (const float4*)skv[d];
        const float4* kv1 = (const float4*)skv[d + 1];
#pragma unroll
        for (int e4 = 0; e4 < 16; e4++) {
            float4 a = kv0[e4], bb = kv1[e4];
            res[e4 * 4 + 0] += qr0 * a.x + qr1 * bb.x;
            res[e4 * 4 + 1] += qr0 * a.y + qr1 * bb.y;
            res[e4 * 4 + 2] += qr0 * a.z + qr1 * bb.z;
            res[e4 * 4 + 3] += qr0 * a.w + qr1 * bb.w;
        }
    }
    const float z = 1.f / (zacc + 1e-6f);

    const size_t yrow = ((size_t)b * NT + t) * 512 + h * 64;
#pragma unroll 8
    for (int e = 0; e < 64; e++) {
        int c = h * 64 + e;
        size_t idx = ((size_t)b * 512 + c) * NT + t;
        float gate = g_qkvo[((size_t)b * 2048 + 1536 + c) * NT + t];
        float yv = (res[e] * z + g_lepe[idx]) * gate;
        __half hh = __float2half(yv);
        g_yth[yrow + e] = hh;
        g_ytl[yrow + e] = __float2half(yv - __half2float(hh));
    }
}

// ---------------- launch ----------------
extern "C" void kernel_launch(void* const* d_in, const int* in_sizes, int n_in,
                              void* d_out, int out_size)
{
    const float* x      = (const float*)d_in[0];
    const float* sinp   = (const float*)d_in[1];
    const float* cosp   = (const float*)d_in[2];
    const float* w_qkvo = (const float*)d_in[3];
    const float* b_qkvo = (const float*)d_in[4];
    const float* w_lepe = (const float*)d_in[5];
    const float* b_lepe = (const float*)d_in[6];
    const float* w_proj = (const float*)d_in[7];
    const float* b_proj = (const float*)d_in[8];
    float* out = (float*)d_out;

    float* qkvo_p = nullptr;
    __half *wqh, *wph, *xth, *xtl, *yth, *ytl;
    cudaGetSymbolAddress((void**)&qkvo_p, g_qkvo);
    cudaGetSymbolAddress((void**)&wqh, g_wqh);
    cudaGetSymbolAddress((void**)&wph, g_wph);
    cudaGetSymbolAddress((void**)&xth, g_xth);
    cudaGetSymbolAddress((void**)&xtl, g_xtl);
    cudaGetSymbolAddress((void**)&yth, g_yth);
    cudaGetSymbolAddress((void**)&ytl, g_ytl);

    cudaFuncSetAttribute(gemm_hmma_kernel, cudaFuncAttributeMaxDynamicSharedMemorySize, GEMM_SMEM);

    zero_kernel<<<(NB * NHEADS * HD * HD + 255) / 256, 256>>>();

    wconv_kernel<<<(2048 * 512 + 255) / 256, 256>>>(w_qkvo, wqh, 2048 * 512);
    wconv_kernel<<<(512 * 512 + 255) / 256, 256>>>(w_proj, wph, 512 * 512);
    xpose_kernel<<<dim3(NT / 32, 512 / 32, NB), 256>>>(x);

    // GEMM1: qkvo[b][2048][4096]
    gemm_hmma_kernel<<<dim3(NT / 128, 2048 / 128, NB), 256, GEMM_SMEM>>>(
        wqh, xth, xtl, b_qkvo, qkvo_p, 2048, NT);

    conv_kernel<<<dim3(NB * CDIM, 16), 256>>>(w_lepe, b_lepe);

    qmean_kernel<<<dim3(NB * NHEADS, 8), 256>>>();
    logits_kernel<<<dim3(NB * NHEADS, 16), 256>>>();
    softmax_kernel<<<NB * NHEADS, 256>>>();

    kv_kernel<<<dim3(NB * NHEADS, 16), 256>>>(sinp, cosp);
    res_kernel<<<dim3(NB * NHEADS, 16), 256>>>(sinp, cosp);

    // GEMM2: out[b][512][4096]
    gemm_hmma_kernel<<<dim3(NT / 128, 512 / 128, NB), 256, GEMM_SMEM>>>(
        wph, yth, ytl, b_proj, out, 512, NT);
}

// round 8
// speedup vs baseline: 2.5088x; 1.2708x over previous
#include <cuda_runtime.h>
#include <cuda_fp16.h>
#include <cstdint>

#define NB 8
#define CDIM 512
#define NHEADS 8
#define HD 64
#define NT 4096           // H*W = 64*64

// ---------------- scratch (device globals: alloc-free) ----------------
// NOTE: q,k channels (c in [0,1024)) of g_qkvo store elu(x)+1 ALREADY APPLIED
// (fused into GEMM1 epilogue). v and gate channels are raw.
__device__ float g_qkvo[(size_t)NB * 2048 * NT];   // 268 MB fp32 qkvo
__device__ float g_lepe[(size_t)NB * CDIM * NT];   // 67 MB
__device__ float g_eff [NB * NHEADS * NT];
__device__ float g_kv  [NB * NHEADS * HD * HD];
__device__ float g_km  [NB * NHEADS * HD];
__device__ float g_qm  [NB * NHEADS * HD];

// fp16 operand buffers for tensor-core GEMMs (single product, pure fp16)
__device__ __half g_wqh[2048 * 512];
__device__ __half g_wph[512 * 512];
__device__ __half g_xth[(size_t)NB * NT * 512];
__device__ __half g_yth[(size_t)NB * NT * 512];

__device__ __forceinline__ float elu1(float x) { return x > 0.f ? x + 1.f : __expf(x); }

__device__ __forceinline__ float warpSum(float v) {
#pragma unroll
    for (int o = 16; o > 0; o >>= 1) v += __shfl_xor_sync(0xffffffffu, v, o);
    return v;
}
__device__ __forceinline__ float warpMax(float v) {
#pragma unroll
    for (int o = 16; o > 0; o >>= 1) v = fmaxf(v, __shfl_xor_sync(0xffffffffu, v, o));
    return v;
}

__device__ __forceinline__ uint32_t smem_u32(const void* p) {
    uint32_t a;
    asm("{ .reg .u64 t; cvta.to.shared.u64 t, %1; cvt.u32.u64 %0, t; }" : "=r"(a) : "l"(p));
    return a;
}
__device__ __forceinline__ void cp_async16(uint32_t dst, const void* src) {
    asm volatile("cp.async.cg.shared.global [%0], [%1], 16;" :: "r"(dst), "l"(src) : "memory");
}
__device__ __forceinline__ void cp_commit() {
    asm volatile("cp.async.commit_group;" ::: "memory");
}
template <int N>
__device__ __forceinline__ void cp_wait() {
    asm volatile("cp.async.wait_group %0;" :: "n"(N) : "memory");
}
__device__ __forceinline__ void ldsm_x4(uint32_t* r, uint32_t addr) {
    asm volatile("ldmatrix.sync.aligned.m8n8.x4.shared.b16 {%0,%1,%2,%3}, [%4];"
                 : "=r"(r[0]), "=r"(r[1]), "=r"(r[2]), "=r"(r[3]) : "r"(addr));
}
__device__ __forceinline__ void mma16816(float* d, const uint32_t* a, uint32_t b0, uint32_t b1) {
    asm volatile("mma.sync.aligned.m16n8k16.row.col.f32.f16.f16.f32 "
                 "{%0,%1,%2,%3}, {%4,%5,%6,%7}, {%8,%9}, {%0,%1,%2,%3};"
                 : "+f"(d[0]), "+f"(d[1]), "+f"(d[2]), "+f"(d[3])
                 : "r"(a[0]), "r"(a[1]), "r"(a[2]), "r"(a[3]), "r"(b0), "r"(b1));
}

// ---------------- zero accumulators (must run every graph replay) ----------------
__global__ void zero_kernel() {
    int i = blockIdx.x * blockDim.x + threadIdx.x;
    if (i < NB * NHEADS * HD * HD) g_kv[i] = 0.f;
    if (i < NB * NHEADS * HD) { g_km[i] = 0.f; g_qm[i] = 0.f; }
}

// ---------------- weight convert: fp32 -> fp16 ----------------
__global__ void wconv_kernel(const float* __restrict__ w, __half* __restrict__ wh, int n)
{
    int i = blockIdx.x * 256 + threadIdx.x;
    if (i < n) wh[i] = __float2half(w[i]);
}

// ---------------- transpose-convert: x[b][k][n] fp32 -> xT[b][n][k] fp16 ----------------
__global__ void __launch_bounds__(256) xpose_kernel(const float* __restrict__ x)
{
    const int b = blockIdx.z;
    const float* src = x + (size_t)b * 512 * NT;
    __half* dh = g_xth + (size_t)b * NT * 512;
    __shared__ float tile[32][33];
    const int n0 = blockIdx.x * 32, k0 = blockIdx.y * 32;
    const int tx = threadIdx.x & 31, ty = threadIdx.x >> 5; // 32x8
#pragma unroll
    for (int i = 0; i < 32; i += 8)
        tile[ty + i][tx] = src[(size_t)(k0 + ty + i) * NT + n0 + tx];
    __syncthreads();
#pragma unroll
    for (int i = 0; i < 32; i += 8) {
        size_t o = (size_t)(n0 + ty + i) * 512 + k0 + tx;
        dh[o] = __float2half(tile[tx][ty + i]);
    }
}

// ---------------- HMMA GEMM: C[b][m][n] = sum_k A[m,k]*B[b][n,k] + bias[m] ----------------
// Pure fp16 operands, single product. 128x128 CTA tile, BK=32, cp.async double buffer.
// Rows with m < elu_rows get elu(.)+1 applied after bias (fused epilogue for q,k).
// SMEM rows padded to 40 halfs (80B): stride 20 words mod 32 -> conflict-free ldmatrix.
#define SROW 40
#define ARR_BYTES (128 * SROW * 2)     // 10240
#define STAGE_BYTES (2 * ARR_BYTES)    // 20480
#define GEMM_SMEM (2 * STAGE_BYTES)    // 40960

__global__ void __launch_bounds__(256, 2) gemm_hmma_kernel(
    const __half* __restrict__ Ah, const __half* __restrict__ Bh,
    const float* __restrict__ bias, float* __restrict__ C, int M, int N, int elu_rows)
{
    const int b = blockIdx.z;
    const int m0 = blockIdx.y * 128, n0 = blockIdx.x * 128;
    const __half* pAh = Ah + (size_t)m0 * 512;
    const __half* pBh = Bh + ((size_t)b * N + n0) * 512;
    float* Cb = C + (size_t)b * M * N;

    extern __shared__ char smem[];
    const uint32_t sb = smem_u32(smem);

    const int tid = threadIdx.x;
    const int lane = tid & 31, wid = tid >> 5;
    const int warp_m = wid & 3, warp_n = wid >> 2;   // 4 x 2 warps -> 32 x 64 per warp

    // cp.async mapping: thread -> (row, half)
    const int lrow = tid >> 1, lhalf = tid & 1;
    const size_t goff = (size_t)lrow * 512 + lhalf * 16;            // elements
    const uint32_t soff = (uint32_t)(lrow * SROW + lhalf * 16) * 2; // bytes

    // ldmatrix per-lane offsets (A and B both non-trans: SMEM is [row][k])
    const int arow = ((lane >> 3) & 1) * 8 + (lane & 7);   // = lane % 16
    const int acol = (lane >> 4) * 8;                      // k element offset
    const int brow = ((lane >> 4) & 1) * 8 + (lane & 7);   // n row within 16
    const int bcol = ((lane >> 3) & 1) * 8;                // k element offset

    float acc[2][8][4];
#pragma unroll
    for (int i = 0; i < 2; i++)
#pragma unroll
        for (int j = 0; j < 8; j++)
#pragma unroll
            for (int q = 0; q < 4; q++) acc[i][j][q] = 0.f;

    // prologue: stage 0
    {
        uint32_t d = sb + soff;
        cp_async16(d + 0 * ARR_BYTES, pAh + goff);
        cp_async16(d + 0 * ARR_BYTES + 16, pAh + goff + 8);
        cp_async16(d + 1 * ARR_BYTES, pBh + goff);
        cp_async16(d + 1 * ARR_BYTES + 16, pBh + goff + 8);
        cp_commit();
    }

    for (int c = 0; c < 16; c++) {
        cp_wait<0>();
        __syncthreads();

        if (c + 1 < 16) {     // issue next chunk; overlaps with compute of chunk c
            const size_t g = goff + (c + 1) * 32;
            uint32_t d = sb + ((c + 1) & 1) * STAGE_BYTES + soff;
            cp_async16(d + 0 * ARR_BYTES, pAh + g);
            cp_async16(d + 0 * ARR_BYTES + 16, pAh + g + 8);
            cp_async16(d + 1 * ARR_BYTES, pBh + g);
            cp_async16(d + 1 * ARR_BYTES + 16, pBh + g + 8);
            cp_commit();
        }

        const uint32_t st = sb + (c & 1) * STAGE_BYTES;
        const uint32_t aB  = st + 0 * ARR_BYTES;  // A
        const uint32_t bB  = st + 1 * ARR_BYTES;  // B

#pragma unroll
        for (int kk = 0; kk < 2; kk++) {
            uint32_t ah[2][4];
#pragma unroll
            for (int mt = 0; mt < 2; mt++) {
                uint32_t ao = (uint32_t)((warp_m * 32 + mt * 16 + arow) * SROW + kk * 16 + acol) * 2;
                ldsm_x4(ah[mt], aB + ao);
            }
#pragma unroll
            for (int g = 0; g < 4; g++) {
                uint32_t bo = (uint32_t)((warp_n * 64 + g * 16 + brow) * SROW + kk * 16 + bcol) * 2;
                uint32_t bh[4];
                ldsm_x4(bh, bB + bo);   // non-trans: SMEM already [n][k] (col-major B)
#pragma unroll
                for (int mt = 0; mt < 2; mt++) {
                    mma16816(acc[mt][g * 2 + 0], ah[mt], bh[0], bh[1]);
                    mma16816(acc[mt][g * 2 + 1], ah[mt], bh[2], bh[3]);
                }
            }
        }
        __syncthreads();   // protect stage (c&1) before it is re-filled at c+1
    }

    // epilogue: bias (+ optional fused elu for q,k rows) + direct float2 stores
#pragma unroll
    for (int mt = 0; mt < 2; mt++) {
        int mA = m0 + warp_m * 32 + mt * 16 + (lane >> 2);
        float bv0 = bias[mA], bv1 = bias[mA + 8];
        const bool e0r = mA < elu_rows, e1r = (mA + 8) < elu_rows;
        float* row0 = Cb + (size_t)mA * N;
        float* row1 = row0 + (size_t)8 * N;
#pragma unroll
        for (int nt = 0; nt < 8; nt++) {
            int n = n0 + warp_n * 64 + nt * 8 + (lane & 3) * 2;
            float a0 = acc[mt][nt][0] + bv0, a1 = acc[mt][nt][1] + bv0;
            float a2 = acc[mt][nt][2] + bv1, a3 = acc[mt][nt][3] + bv1;
            if (e0r) { a0 = elu1(a0); a1 = elu1(a1); }
            if (e1r) { a2 = elu1(a2); a3 = elu1(a3); }
            *(float2*)(row0 + n) = make_float2(a0, a1);
            *(float2*)(row1 + n) = make_float2(a2, a3);
        }
    }
}

// ---------------- depthwise 5x5 conv on v channels -> g_lepe ----------------
__global__ void __launch_bounds__(256) conv_kernel(
    const float* __restrict__ w_lepe, const float* __restrict__ b_lepe)
{
    const int bc = blockIdx.x;
    const int b = bc >> 9, c = bc & 511;
    __shared__ float wsh[25];
    const int tid = threadIdx.x;
    if (tid < 25) wsh[tid] = w_lepe[c * 25 + tid];
    __syncthreads();

    const int y = blockIdx.y * 4 + (tid >> 6);
    const int xw = tid & 63;
    const float* Vp = g_qkvo + ((size_t)b * 2048 + 1024 + c) * NT;

    float acc = b_lepe[c];
#pragma unroll
    for (int i = 0; i < 5; i++) {
        int yy = y + i - 2;
        if (yy < 0 || yy >= 64) continue;
#pragma unroll
        for (int j = 0; j < 5; j++) {
            int xx = xw + j - 2;
            if (xx < 0 || xx >= 64) continue;
            acc += wsh[i * 5 + j] * Vp[yy * 64 + xx];
        }
    }
    g_lepe[((size_t)b * 512 + c) * NT + y * 64 + xw] = acc;
}

// ---------------- split stats: qmean -> logits -> softmax ----------------
// Q,K channels already hold elu(.)+1 (fused in GEMM1 epilogue).
__global__ void __launch_bounds__(256) qmean_kernel()
{
    const int bh = blockIdx.x;
    const int b = bh >> 3, h = bh & 7;
    const float* Q = g_qkvo + ((size_t)b * 2048 + h * 64) * NT;
    __shared__ float s[64];
    const int tid = threadIdx.x, lane = tid & 31;
    if (tid < 64) s[tid] = 0.f;
    __syncthreads();
    const int t0 = blockIdx.y * 512;
    for (int d = 0; d < 64; d++) {
        float p = Q[(size_t)d * NT + t0 + tid] + Q[(size_t)d * NT + t0 + 256 + tid];
        p = warpSum(p);
        if (lane == 0) atomicAdd(&s[d], p);
    }
    __syncthreads();
    if (tid < 64) atomicAdd(&g_qm[bh * 64 + tid], s[tid]);
}

__global__ void __launch_bounds__(256) logits_kernel()
{
    const int bh = blockIdx.x;
    const int b = bh >> 3, h = bh & 7;
    const float* Kp = g_qkvo + ((size_t)b * 2048 + 512 + h * 64) * NT;
    __shared__ float sq[64];
    const int tid = threadIdx.x;
    if (tid < 64) sq[tid] = g_qm[bh * 64 + tid] * (1.f / NT);
    __syncthreads();
    const int t = blockIdx.y * 256 + tid;
    float l = 0.f;
#pragma unroll 8
    for (int d = 0; d < 64; d++) l += sq[d] * Kp[(size_t)d * NT + t];
    g_eff[bh * NT + t] = l * 0.125f;   // SCALE
}

__global__ void __launch_bounds__(256) softmax_kernel()
{
    const int bh = blockIdx.x;
    const int tid = threadIdx.x;
    const int lane = tid & 31, wid = tid >> 5;
    __shared__ float red[8];
    float l[16];
#pragma unroll
    for (int i = 0; i < 16; i++) l[i] = g_eff[bh * NT + tid + i * 256];
    float mx = -1e30f;
#pragma unroll
    for (int i = 0; i < 16; i++) mx = fmaxf(mx, l[i]);
    mx = warpMax(mx);
    if (lane == 0) red[wid] = mx;
    __syncthreads();
    if (tid == 0) { float m = red[0]; for (int w = 1; w < 8; w++) m = fmaxf(m, red[w]); red[0] = m; }
    __syncthreads();
    mx = red[0];
    __syncthreads();
    float s = 0.f;
#pragma unroll
    for (int i = 0; i < 16; i++) s += __expf(l[i] - mx);
    s = warpSum(s);
    if (lane == 0) red[wid] = s;
    __syncthreads();
    if (tid == 0) { float ss = 0.f; for (int w = 0; w < 8; w++) ss += red[w]; red[0] = ss; }
    __syncthreads();
    const float inv = 1.f / red[0];
#pragma unroll
    for (int i = 0; i < 16; i++)
        g_eff[bh * NT + tid + i * 256] = __expf(l[i] - mx) * inv;
}

// ---------------- kv[d,e] = sum_t rope(k*eff)[t,d]*v[t,e];  km[d] = sum_t k*eff ----------------
__global__ void __launch_bounds__(256) kv_kernel(
    const float* __restrict__ sinp, const float* __restrict__ cosp)
{
    const int bh = blockIdx.x;
    const int b = bh >> 3, h = bh & 7;
    const int chunk = blockIdx.y;   // 16 chunks of 256 t
    const float* Kp  = g_qkvo + ((size_t)b * 2048 +  512 + h * 64) * NT;   // elu'd k
    const float* Vp  = g_qkvo + ((size_t)b * 2048 + 1024 + h * 64) * NT;
    const float* eff = g_eff + bh * NT;

    __shared__ float sk[64][65];
    __shared__ float sv[64][65];

    const int tid = threadIdx.x;
    const int ttl = tid & 63;
    const int drow = tid >> 6;
    const int d0 = (tid & 15) * 4, e0 = (tid >> 4) * 4;

    float acc[4][4];
#pragma unroll
    for (int i = 0; i < 4; i++)
#pragma unroll
        for (int j = 0; j < 4; j++) acc[i][j] = 0.f;
    float kmacc = 0.f;

    for (int tile = 0; tile < 4; tile++) {
        const int t0 = chunk * 256 + tile * 64;
        const float effv = eff[t0 + ttl];
#pragma unroll
        for (int r = 0; r < 16; r++) {
            int d = drow + r * 4;
            sk[ttl][d] = Kp[(size_t)d * NT + t0 + ttl] * effv;
            sv[ttl][d] = Vp[(size_t)d * NT + t0 + ttl];
        }
        __syncthreads();

        if (tid < 64) {
#pragma unroll 8
            for (int tt = 0; tt < 64; tt++) kmacc += sk[tt][tid];
        }
        float r0[8], r1[8];
        const int t = t0 + ttl;
#pragma unroll
        for (int r = 0; r < 8; r++) {
            int pr = drow + r * 4;
            int d = 2 * pr;
            float a  = sk[ttl][d];
            float bb = sk[ttl][d + 1];
            float c0 = cosp[t * 64 + d],     s0 = sinp[t * 64 + d];
            float c1 = cosp[t * 64 + d + 1], s1 = sinp[t * 64 + d + 1];
            r0[r] = a * c0 - bb * s0;
            r1[r] = bb * c1 + a * s1;
        }
        __syncthreads();
#pragma unroll
        for (int r = 0; r < 8; r++) {
            int d = 2 * (drow + r * 4);
            sk[ttl][d]     = r0[r];
            sk[ttl][d + 1] = r1[r];
        }
        __syncthreads();

#pragma unroll 4
        for (int tt = 0; tt < 64; tt++) {
            float kk[4], vv[4];
#pragma unroll
            for (int j = 0; j < 4; j++) { kk[j] = sk[tt][d0 + j]; vv[j] = sv[tt][e0 + j]; }
#pragma unroll
            for (int i = 0; i < 4; i++)
#pragma unroll
                for (int j = 0; j < 4; j++) acc[i][j] += kk[i] * vv[j];
        }
        __syncthreads();
    }

    float* kvout = g_kv + (size_t)bh * HD * HD;
#pragma unroll
    for (int i = 0; i < 4; i++)
#pragma unroll
        for (int j = 0; j < 4; j++)
            atomicAdd(&kvout[(d0 + i) * 64 + e0 + j], acc[i][j]);
    if (tid < 64) atomicAdd(&g_km[bh * 64 + tid], kmacc);
}

// ---------------- res: y = (attn*z + lepe)*gate -> yT fp16 ----------------
__global__ void __launch_bounds__(256) res_kernel(
    const float* __restrict__ sinp, const float* __restrict__ cosp)
{
    const int bh = blockIdx.x;
    const int b = bh >> 3, h = bh & 7;
    const int tid = threadIdx.x;
    const int t = blockIdx.y * 256 + tid;
    const float* Q = g_qkvo + ((size_t)b * 2048 + h * 64) * NT;   // elu'd q

    __shared__ float skv[64][64];
    __shared__ float skm[64];
#pragma unroll
    for (int r = 0; r < 16; r++)
        ((float*)skv)[tid + r * 256] = g_kv[(size_t)bh * 4096 + tid + r * 256];
    if (tid < 64) skm[tid] = g_km[bh * 64 + tid];
    __syncthreads();

    float res[64];
#pragma unroll
    for (int e = 0; e < 64; e++) res[e] = 0.f;
    float zacc = 0.f;

    for (int p = 0; p < 32; p++) {
        const int d = 2 * p;
        float q0 = Q[(size_t)d * NT + t];
        float q1 = Q[(size_t)(d + 1) * NT + t];
        zacc += q0 * skm[d] + q1 * skm[d + 1];
        float c0 = cosp[t * 64 + d],     s0 = sinp[t * 64 + d];
        float c1 = cosp[t * 64 + d + 1], s1 = sinp[t * 64 + d + 1];
        float qr0 = q0 * c0 - q1 * s0;
        float qr1 = q1 * c1 + q0 * s1;
        const float4* kv0 = (const float4*)skv[d];
        const float4* kv1 = (const float4*)skv[d + 1];
#pragma unroll
        for (int e4 = 0; e4 < 16; e4++) {
            float4 a = kv0[e4], bb = kv1[e4];
            res[e4 * 4 + 0] += qr0 * a.x + qr1 * bb.x;
            res[e4 * 4 + 1] += qr0 * a.y + qr1 * bb.y;
            res[e4 * 4 + 2] += qr0 * a.z + qr1 * bb.z;
            res[e4 * 4 + 3] += qr0 * a.w + qr1 * bb.w;
        }
    }
    const float z = 1.f / (zacc + 1e-6f);

    const size_t yrow = ((size_t)b * NT + t) * 512 + h * 64;
#pragma unroll 8
    for (int e = 0; e < 64; e++) {
        int c = h * 64 + e;
        size_t idx = ((size_t)b * 512 + c) * NT + t;
        float gate = g_qkvo[((size_t)b * 2048 + 1536 + c) * NT + t];
        float yv = (res[e] * z + g_lepe[idx]) * gate;
        g_yth[yrow + e] = __float2half(yv);
    }
}

// ---------------- launch ----------------
extern "C" void kernel_launch(void* const* d_in, const int* in_sizes, int n_in,
                              void* d_out, int out_size)
{
    const float* x      = (const float*)d_in[0];
    const float* sinp   = (const float*)d_in[1];
    const float* cosp   = (const float*)d_in[2];
    const float* w_qkvo = (const float*)d_in[3];
    const float* b_qkvo = (const float*)d_in[4];
    const float* w_lepe = (const float*)d_in[5];
    const float* b_lepe = (const float*)d_in[6];
    const float* w_proj = (const float*)d_in[7];
    const float* b_proj = (const float*)d_in[8];
    float* out = (float*)d_out;

    float* qkvo_p = nullptr;
    __half *wqh, *wph, *xth, *yth;
    cudaGetSymbolAddress((void**)&qkvo_p, g_qkvo);
    cudaGetSymbolAddress((void**)&wqh, g_wqh);
    cudaGetSymbolAddress((void**)&wph, g_wph);
    cudaGetSymbolAddress((void**)&xth, g_xth);
    cudaGetSymbolAddress((void**)&yth, g_yth);

    cudaFuncSetAttribute(gemm_hmma_kernel, cudaFuncAttributeMaxDynamicSharedMemorySize, GEMM_SMEM);

    zero_kernel<<<(NB * NHEADS * HD * HD + 255) / 256, 256>>>();

    wconv_kernel<<<(2048 * 512 + 255) / 256, 256>>>(w_qkvo, wqh, 2048 * 512);
    wconv_kernel<<<(512 * 512 + 255) / 256, 256>>>(w_proj, wph, 512 * 512);
    xpose_kernel<<<dim3(NT / 32, 512 / 32, NB), 256>>>(x);

    // GEMM1: qkvo[b][2048][4096], elu fused for q,k rows (m < 1024)
    gemm_hmma_kernel<<<dim3(NT / 128, 2048 / 128, NB), 256, GEMM_SMEM>>>(
        wqh, xth, b_qkvo, qkvo_p, 2048, NT, 1024);

    conv_kernel<<<dim3(NB * CDIM, 16), 256>>>(w_lepe, b_lepe);

    qmean_kernel<<<dim3(NB * NHEADS, 8), 256>>>();
    logits_kernel<<<dim3(NB * NHEADS, 16), 256>>>();
    softmax_kernel<<<NB * NHEADS, 256>>>();

    kv_kernel<<<dim3(NB * NHEADS, 16), 256>>>(sinp, cosp);
    res_kernel<<<dim3(NB * NHEADS, 16), 256>>>(sinp, cosp);

    // GEMM2: out[b][512][4096], no elu
    gemm_hmma_kernel<<<dim3(NT / 128, 512 / 128, NB), 256, GEMM_SMEM>>>(
        wph, yth, b_proj, out, 512, NT, 0);
}